// round 6
// baseline (speedup 1.0000x reference)
#include <cuda_runtime.h>
#include <cuda_bf16.h>
#include <math.h>
#include <stdint.h>

// Problem constants
#define NN   32768      // nodes
#define HH   256        // hidden
#define FD   128        // input feature dim
#define BB   256        // graphs
#define MAXN 128        // nodes per graph
#define EE   524288     // edges
#define EPG  2048       // edges per graph (EE/BB)

// ======================= PTX helpers (baseline compute_100 only) =======================
__device__ __forceinline__ uint32_t smem_to_u32(const void* smem_ptr) {
    uint32_t addr;
    asm("{ .reg .u64 tmp; cvta.to.shared.u64 tmp, %1; cvt.u32.u64 %0, tmp; }"
        : "=r"(addr) : "l"(smem_ptr));
    return addr;
}
__device__ __forceinline__ void ldsm4(uint32_t* r, uint32_t addr) {
    asm volatile("ldmatrix.sync.aligned.m8n8.x4.shared.b16 {%0,%1,%2,%3}, [%4];"
        : "=r"(r[0]), "=r"(r[1]), "=r"(r[2]), "=r"(r[3]) : "r"(addr));
}
__device__ __forceinline__ void mma16816(float* d, const uint32_t* a, uint32_t b0, uint32_t b1) {
    asm volatile(
        "mma.sync.aligned.m16n8k16.row.col.f32.bf16.bf16.f32 "
        "{%0,%1,%2,%3}, {%4,%5,%6,%7}, {%8,%9}, {%0,%1,%2,%3};"
        : "+f"(d[0]), "+f"(d[1]), "+f"(d[2]), "+f"(d[3])
        : "r"(a[0]), "r"(a[1]), "r"(a[2]), "r"(a[3]), "r"(b0), "r"(b1));
}
__device__ __forceinline__ void cp16(uint32_t s, const void* g) {
    asm volatile("cp.async.cg.shared.global [%0], [%1], 16;" :: "r"(s), "l"(g) : "memory");
}
__device__ __forceinline__ void cp_commit() {
    asm volatile("cp.async.commit_group;" ::: "memory");
}
template<int NG> __device__ __forceinline__ void cp_wait() {
    asm volatile("cp.async.wait_group %0;" :: "n"(NG) : "memory");
}

// ---------------- scratch (device globals) ----------------
__device__ __align__(256) float g_bufA[(size_t)NN * HH];
__device__ __align__(256) float g_bufB[(size_t)NN * HH];
__device__ __align__(256) float g_z[(size_t)NN * HH];
__device__ __align__(256) float g_sc[(size_t)NN * HH];
__device__ float g_dinv[NN];
__device__ int   g_deg[NN];
__device__ int   g_rowstart[NN];
__device__ int   g_cursor[NN];
__device__ int   g_csr_src[EE];
__device__ float g_csr_norm[EE];
__device__ float g_stats[2 * HH];

// bf16 hi/lo operand buffers
__device__ __align__(256) __nv_bfloat16 g_p0hi[(size_t)NN * HH];
__device__ __align__(256) __nv_bfloat16 g_p0lo[(size_t)NN * HH];
__device__ __align__(256) __nv_bfloat16 g_p1hi[(size_t)NN * HH];
__device__ __align__(256) __nv_bfloat16 g_p1lo[(size_t)NN * HH];
__device__ __align__(256) __nv_bfloat16 g_s0hi[BB * HH];
__device__ __align__(256) __nv_bfloat16 g_s0lo[BB * HH];
__device__ __align__(256) __nv_bfloat16 g_s1hi[BB * HH];
__device__ __align__(256) __nv_bfloat16 g_s1lo[BB * HH];
__device__ __align__(256) __nv_bfloat16 g_whi[10 * 65536];  // 10 transposed weights
__device__ __align__(256) __nv_bfloat16 g_wlo[10 * 65536];

// ---------------- precompute: degrees, dinv, CSR ----------------
__global__ void k_zero_deg() {
    int n = blockIdx.x * 256 + threadIdx.x;
    if (n < NN) g_deg[n] = 0;
}
__global__ void k_count_deg(const int* __restrict__ dst) {
    int e = blockIdx.x * 256 + threadIdx.x;
    if (e >= EE) return;
    int g = e >> 11;
    atomicAdd(&g_deg[g * MAXN + dst[e]], 1);
}
// per-graph CTA: exclusive scan of edge degrees + dinv
__global__ void k_scan_rows() {
    int g = blockIdx.x;
    int t = threadIdx.x;
    int n = g * MAXN + t;
    __shared__ int s[MAXN];
    int d = g_deg[n];
    g_dinv[n] = rsqrtf((float)(d + 1));   // self loop adds 1
    s[t] = d;
    __syncthreads();
    for (int off = 1; off < MAXN; off <<= 1) {
        int v = (t >= off) ? s[t - off] : 0;
        __syncthreads();
        s[t] += v;
        __syncthreads();
    }
    int start = g * EPG + s[t] - d;
    g_rowstart[n] = start;
    g_cursor[n] = start;
}
__global__ void k_fill_csr(const int* __restrict__ src, const int* __restrict__ dst) {
    int e = blockIdx.x * 256 + threadIdx.x;
    if (e >= EE) return;
    int g = e >> 11;
    int s = src[e], d = dst[e];
    int slot = atomicAdd(&g_cursor[g * MAXN + d], 1);
    g_csr_src[slot] = s;
    g_csr_norm[slot] = g_dinv[g * MAXN + s] * g_dinv[g * MAXN + d];
}

// ---------------- fp32 -> bf16 hi/lo converts ----------------
__device__ __forceinline__ void split_bf16(float v, __nv_bfloat16& h, __nv_bfloat16& l) {
    h = __float2bfloat16(v);
    l = __float2bfloat16(v - __bfloat162float(h));
}
__device__ __forceinline__ void emit4(__nv_bfloat16* hi, __nv_bfloat16* lo, size_t o,
                                      float a, float b, float c, float d) {
    __nv_bfloat16 h0, l0, h1, l1, h2, l2, h3, l3;
    split_bf16(a, h0, l0); split_bf16(b, h1, l1);
    split_bf16(c, h2, l2); split_bf16(d, h3, l3);
    __nv_bfloat162 hv0 = {h0, h1}, hv1 = {h2, h3};
    __nv_bfloat162 lv0 = {l0, l1}, lv1 = {l2, l3};
    *(__nv_bfloat162*)(hi + o) = hv0;
    *(__nv_bfloat162*)(hi + o + 2) = hv1;
    *(__nv_bfloat162*)(lo + o) = lv0;
    *(__nv_bfloat162*)(lo + o + 2) = lv1;
}
__global__ void a_conv(const float* __restrict__ A, __nv_bfloat16* __restrict__ hi,
                       __nv_bfloat16* __restrict__ lo, int n4) {
    int i = blockIdx.x * 256 + threadIdx.x;
    if (i >= n4) return;
    float4 v = ((const float4*)A)[i];
    emit4(hi, lo, (size_t)i * 4, v.x, v.y, v.z, v.w);
}
// all 10 weights in one launch: W[K,N] fp32 -> hi/lo[N,K] bf16 at slot w*65536
struct WList { const float* w[10]; int kd[10]; int nd[10]; };
__global__ void w_conv_all(WList wl, __nv_bfloat16* __restrict__ hi,
                           __nv_bfloat16* __restrict__ lo) {
    int widx = blockIdx.y;
    int i = blockIdx.x * 256 + threadIdx.x;
    int Kd = wl.kd[widx], Nd = wl.nd[widx];
    if (i >= Kd * Nd) return;
    int k = i / Nd, n = i - k * Nd;
    __nv_bfloat16 h, l;
    split_bf16(wl.w[widx][i], h, l);
    hi[(size_t)widx * 65536 + (size_t)n * Kd + k] = h;
    lo[(size_t)widx * 65536 + (size_t)n * Kd + k] = l;
}

// ======================= mma.sync split-x3 GEMM =======================
// C[M,Ncols] = A[M,K] @ B[Ncols,K]^T via bf16 hi/lo x3, fp32 accumulate.
// CTA: 128(M) x 128(N) tile, 8 warps (4x2), warp tile 32x64; 2 CTAs/SM.
// K chunks of 32, cp.async double-buffered. SMEM rows padded to 80B.
// STATS: per-column sum/sumsq of the (post-bias/relu) output -> g_stats.
#define ROWB   80
#define MATB   10240            // 128 rows * 80B
#define STAGEB 40960            // 4 matrices (Ahi,Alo,Bhi,Blo)
template<bool ADJ, bool STATS>
__global__ void __launch_bounds__(256, 2)
mma_gemm(const __nv_bfloat16* __restrict__ Ahi, const __nv_bfloat16* __restrict__ Alo,
         const __nv_bfloat16* __restrict__ Bhi, const __nv_bfloat16* __restrict__ Blo,
         const float* __restrict__ bias, float* __restrict__ Cf,
         __nv_bfloat16* __restrict__ Chi, __nv_bfloat16* __restrict__ Clo,
         int K, int Ncols, int relu)
{
    extern __shared__ char smem[];
    const uint32_t sb = smem_to_u32(smem);
    const int tid = threadIdx.x;
    const int lane = tid & 31;
    const int wid = tid >> 5;
    const int warp_m = wid & 3;        // 4 warps along M
    const int warp_n = wid >> 2;       // 2 warps along N
    const int mrow0 = blockIdx.x * 128;
    const int bn0 = blockIdx.y * 128;
    const int brow0 = ADJ ? mrow0 : bn0;

    const __nv_bfloat16* baseA_hi = Ahi + (size_t)mrow0 * K;
    const __nv_bfloat16* baseA_lo = Alo + (size_t)mrow0 * K;
    const __nv_bfloat16* baseB_hi = Bhi + (size_t)brow0 * K;
    const __nv_bfloat16* baseB_lo = Blo + (size_t)brow0 * K;

    float acc[2][8][4];
#pragma unroll
    for (int mt = 0; mt < 2; mt++)
#pragma unroll
        for (int nt = 0; nt < 8; nt++)
#pragma unroll
            for (int v = 0; v < 4; v++) acc[mt][nt][v] = 0.f;

    auto load_chunk = [&](int c, int stage) {
        const int kc = c << 5;
        const uint32_t sbase = sb + stage * STAGEB;
#pragma unroll
        for (int t = 0; t < 8; t++) {
            int i = t * 256 + tid;
            int mat = i >> 9;               // constant per unrolled t
            int r = (i >> 2) & 127;
            int q = i & 3;
            const __nv_bfloat16* g;
            if      (mat == 0) g = baseA_hi + (size_t)r * K + kc + q * 8;
            else if (mat == 1) g = baseA_lo + (size_t)r * K + kc + q * 8;
            else if (mat == 2) g = baseB_hi + (size_t)r * K + kc + q * 8;
            else               g = baseB_lo + (size_t)r * K + kc + q * 8;
            cp16(sbase + mat * MATB + r * ROWB + q * 16, g);
        }
    };

    auto compute_chunk = [&](int stage) {
        const uint32_t sA = sb + stage * STAGEB;
        const uint32_t sB = sA + 2 * MATB;
#pragma unroll
        for (int ks = 0; ks < 2; ks++) {
            const uint32_t koff = ks * 32 + (lane >> 4) * 16;
            uint32_t ahi[2][4], alo[2][4];
#pragma unroll
            for (int mt = 0; mt < 2; mt++) {
                uint32_t ad = sA + (uint32_t)((warp_m * 32 + mt * 16 + (lane & 15)) * ROWB) + koff;
                ldsm4(ahi[mt], ad);
                ldsm4(alo[mt], ad + MATB);
            }
            // B fragments in two halves (register pressure: enables 2 CTAs/SM)
#pragma unroll
            for (int half = 0; half < 2; half++) {
                uint32_t bhiR[2][4], bloR[2][4];
#pragma unroll
                for (int g2 = 0; g2 < 2; g2++) {
                    uint32_t ad = sB + (uint32_t)((warp_n * 64 + (half * 2 + g2) * 16
                                   + (lane & 15)) * ROWB) + koff;
                    ldsm4(bhiR[g2], ad);
                    ldsm4(bloR[g2], ad + MATB);
                }
#pragma unroll
                for (int mt = 0; mt < 2; mt++)
#pragma unroll
                    for (int nt = 0; nt < 4; nt++) {
                        int g2 = nt >> 1, s = nt & 1;
                        float* ac = acc[mt][half * 4 + nt];
                        mma16816(ac, ahi[mt], bhiR[g2][s], bhiR[g2][s + 2]);
                        mma16816(ac, ahi[mt], bloR[g2][s], bloR[g2][s + 2]);
                        mma16816(ac, alo[mt], bhiR[g2][s], bhiR[g2][s + 2]);
                    }
            }
        }
    };

    const int nch = K >> 5;
    load_chunk(0, 0);
    cp_commit();
    for (int c = 0; c < nch; c++) {
        if (c + 1 < nch) {
            load_chunk(c + 1, (c + 1) & 1);
            cp_commit();
            cp_wait<1>();
        } else {
            cp_wait<0>();
        }
        __syncthreads();
        compute_chunk(c & 1);
        __syncthreads();
    }

    // ---- epilogue (register-resident) ----
    float* sst = (float*)smem;   // 256 floats: [0:128) sums, [128:256) sumsq (local cols)
    if (STATS) {
        if (tid < 256) sst[tid] = 0.f;
        __syncthreads();
    }
    float colsum[16], colsq[16];
    if (STATS) {
#pragma unroll
        for (int k = 0; k < 16; k++) { colsum[k] = 0.f; colsq[k] = 0.f; }
    }
    const int r0 = lane >> 2;
    const int cq = (lane & 3) * 2;
#pragma unroll
    for (int mt = 0; mt < 2; mt++) {
#pragma unroll
        for (int nt = 0; nt < 8; nt++) {
            int col = bn0 + warp_n * 64 + nt * 8 + cq;
            float bv0 = 0.f, bv1 = 0.f;
            if (bias) { bv0 = bias[col]; bv1 = bias[col + 1]; }
#pragma unroll
            for (int h = 0; h < 2; h++) {
                int row = mrow0 + warp_m * 32 + mt * 16 + r0 + h * 8;
                float v0 = acc[mt][nt][h * 2 + 0] + bv0;
                float v1 = acc[mt][nt][h * 2 + 1] + bv1;
                if (relu) { v0 = fmaxf(v0, 0.f); v1 = fmaxf(v1, 0.f); }
                if (STATS) {
                    colsum[nt * 2] += v0;     colsq[nt * 2] = fmaf(v0, v0, colsq[nt * 2]);
                    colsum[nt * 2 + 1] += v1; colsq[nt * 2 + 1] = fmaf(v1, v1, colsq[nt * 2 + 1]);
                }
                if (ADJ) {
                    v0 = 1.f / (1.f + __expf(-v0));
                    v1 = 1.f / (1.f + __expf(-v1));
                    int rl = row - mrow0;
                    int cl = col;
                    if (rl == cl) v0 = 0.f;
                    if (rl == cl + 1) v1 = 0.f;
                    *(float2*)(Cf + (size_t)blockIdx.x * (MAXN * MAXN)
                               + (size_t)rl * MAXN + cl) = make_float2(v0, v1);
                } else {
                    size_t o = (size_t)row * Ncols + col;
                    if (Cf) *(float2*)(Cf + o) = make_float2(v0, v1);
                    if (Chi) {
                        __nv_bfloat16 h0, l0, h1, l1;
                        split_bf16(v0, h0, l0);
                        split_bf16(v1, h1, l1);
                        __nv_bfloat162 ph = {h0, h1}, pl = {l0, l1};
                        *(__nv_bfloat162*)(Chi + o) = ph;
                        *(__nv_bfloat162*)(Clo + o) = pl;
                    }
                }
            }
        }
    }
    if (STATS) {
#pragma unroll
        for (int nt = 0; nt < 8; nt++) {
            int cl = warp_n * 64 + nt * 8 + cq;
            atomicAdd(&sst[cl],           colsum[nt * 2]);
            atomicAdd(&sst[cl + 1],       colsum[nt * 2 + 1]);
            atomicAdd(&sst[128 + cl],     colsq[nt * 2]);
            atomicAdd(&sst[128 + cl + 1], colsq[nt * 2 + 1]);
        }
        __syncthreads();
        if (tid < 128) {
            atomicAdd(&g_stats[bn0 + tid], sst[tid]);
            atomicAdd(&g_stats[256 + bn0 + tid], sst[128 + tid]);
        }
    }
}

// ---------------- per-graph GCN aggregation + fused BN stats ----------------
__global__ void __launch_bounds__(256)
aggregate(const float* __restrict__ hw, float* __restrict__ outp, int do_stats) {
    extern __shared__ float sh[];           // 128 x 128 fp32 (64KB)
    __shared__ float sstat[512];
    int g = blockIdx.x;
    int tid = threadIdx.x;
    int lane = tid & 31;
    int w = tid >> 5;
    int nbase = g * MAXN;
    if (do_stats) { sstat[tid] = 0.f; sstat[tid + 256] = 0.f; }
    for (int q = 0; q < 2; q++) {
        __syncthreads();
        int c0 = q * 128;
        for (int i = tid; i < 128 * 32; i += 256) {
            ((float4*)sh)[i] =
                *(const float4*)(hw + (size_t)(nbase + (i >> 5)) * HH + c0 + (i & 31) * 4);
        }
        __syncthreads();
        float ps0 = 0.f, ps1 = 0.f, ps2 = 0.f, ps3 = 0.f;
        float pq0 = 0.f, pq1 = 0.f, pq2 = 0.f, pq3 = 0.f;
        for (int n = w; n < MAXN; n += 8) {
            int gn = nbase + n;
            int rs = g_rowstart[gn];
            int cnt = g_deg[gn];
            float di = g_dinv[gn];
            float sl = di * di;
            float4 self = *(const float4*)&sh[n * 128 + lane * 4];
            float a0 = self.x * sl, a1 = self.y * sl, a2 = self.z * sl, a3 = self.w * sl;
            for (int e = 0; e < cnt; e++) {
                int s = __ldg(&g_csr_src[rs + e]);
                float nm = __ldg(&g_csr_norm[rs + e]);
                float4 p = *(const float4*)&sh[s * 128 + lane * 4];
                a0 = fmaf(p.x, nm, a0);
                a1 = fmaf(p.y, nm, a1);
                a2 = fmaf(p.z, nm, a2);
                a3 = fmaf(p.w, nm, a3);
            }
            *(float4*)(outp + (size_t)gn * HH + c0 + lane * 4) = make_float4(a0, a1, a2, a3);
            if (do_stats) {
                ps0 += a0; ps1 += a1; ps2 += a2; ps3 += a3;
                pq0 = fmaf(a0, a0, pq0); pq1 = fmaf(a1, a1, pq1);
                pq2 = fmaf(a2, a2, pq2); pq3 = fmaf(a3, a3, pq3);
            }
        }
        if (do_stats) {
            int c = c0 + lane * 4;
            atomicAdd(&sstat[c + 0], ps0); atomicAdd(&sstat[c + 1], ps1);
            atomicAdd(&sstat[c + 2], ps2); atomicAdd(&sstat[c + 3], ps3);
            atomicAdd(&sstat[256 + c + 0], pq0); atomicAdd(&sstat[256 + c + 1], pq1);
            atomicAdd(&sstat[256 + c + 2], pq2); atomicAdd(&sstat[256 + c + 3], pq3);
        }
    }
    if (do_stats) {
        __syncthreads();
        atomicAdd(&g_stats[tid], sstat[tid]);
        atomicAdd(&g_stats[tid + 256], sstat[tid + 256]);
    }
}

// ---------------- BatchNorm apply (vectorized, + bf16 emit) ----------------
__global__ void k_zero_stats() {
    int t = threadIdx.x;
    if (t < 2 * HH) g_stats[t] = 0.f;
}
// mode 0: out = bn(x); mode 1: out = relu(relu(bn(x)) + res). float4 per thread.
__global__ void bn_apply(const float* __restrict__ xin, const float* __restrict__ res,
                         const float* __restrict__ gam, const float* __restrict__ bet,
                         float* __restrict__ outp,
                         __nv_bfloat16* __restrict__ ohi, __nv_bfloat16* __restrict__ olo,
                         int mode)
{
    size_t i4 = ((size_t)blockIdx.x * 256 + threadIdx.x) * 4;
    int col = (int)(i4 & 255);
    const float invN = 1.0f / (float)NN;
    float a[4], bp[4];
#pragma unroll
    for (int k = 0; k < 4; k++) {
        float m = g_stats[col + k] * invN;
        float var = fmaxf(g_stats[HH + col + k] * invN - m * m, 0.f);
        float aa = gam[col + k] * rsqrtf(var + 1e-5f);
        a[k] = aa;
        bp[k] = bet[col + k] - m * aa;
    }
    float4 xv = *(const float4*)(xin + i4);
    float v[4] = { fmaf(xv.x, a[0], bp[0]), fmaf(xv.y, a[1], bp[1]),
                   fmaf(xv.z, a[2], bp[2]), fmaf(xv.w, a[3], bp[3]) };
    if (mode == 1) {
        float4 rv = *(const float4*)(res + i4);
        v[0] = fmaxf(fmaxf(v[0], 0.f) + rv.x, 0.f);
        v[1] = fmaxf(fmaxf(v[1], 0.f) + rv.y, 0.f);
        v[2] = fmaxf(fmaxf(v[2], 0.f) + rv.z, 0.f);
        v[3] = fmaxf(fmaxf(v[3], 0.f) + rv.w, 0.f);
    }
    if (outp) *(float4*)(outp + i4) = make_float4(v[0], v[1], v[2], v[3]);
    if (ohi) emit4(ohi, olo, i4, v[0], v[1], v[2], v[3]);
}

// ---------------- fused row L2 normalize + per-graph max pool ----------------
// One CTA per graph. Phase 1: row norms. Phase 2: per-column normalize+max.
__global__ void __launch_bounds__(256)
l2norm_pool(const float* __restrict__ zin, float* __restrict__ out_z,
            __nv_bfloat16* __restrict__ ohi, __nv_bfloat16* __restrict__ olo,
            float* __restrict__ out_zg,
            __nv_bfloat16* __restrict__ shi, __nv_bfloat16* __restrict__ slo)
{
    __shared__ float rinv[MAXN];
    int g = blockIdx.x;
    int tid = threadIdx.x;
    int lane = tid & 31;
    int w = tid >> 5;
    const float* base = zin + (size_t)g * MAXN * HH;
    for (int r = w; r < MAXN; r += 8) {
        const float4* p = (const float4*)(base + (size_t)r * HH);
        float4 v0 = p[lane], v1 = p[lane + 32];
        float s = v0.x * v0.x + v0.y * v0.y + v0.z * v0.z + v0.w * v0.w
                + v1.x * v1.x + v1.y * v1.y + v1.z * v1.z + v1.w * v1.w;
#pragma unroll
        for (int o = 16; o > 0; o >>= 1) s += __shfl_xor_sync(0xffffffffu, s, o);
        if (lane == 0) rinv[r] = 1.f / fmaxf(sqrtf(s), 1e-12f);
    }
    __syncthreads();
    int c = tid;                       // 256 cols, one per thread
    float mx = -1e30f;
    for (int r = 0; r < MAXN; r++) {
        float v = base[(size_t)r * HH + c] * rinv[r];
        mx = fmaxf(mx, v);
        size_t o = (size_t)(g * MAXN + r) * HH + c;
        out_z[o] = v;
        __nv_bfloat16 h, l;
        split_bf16(v, h, l);
        ohi[o] = h; olo[o] = l;
    }
    int o2 = g * HH + c;
    out_zg[o2] = mx;
    __nv_bfloat16 h, l;
    split_bf16(mx, h, l);
    shi[o2] = h; slo[o2] = l;
}

// ---------------- launcher ----------------
extern "C" void kernel_launch(void* const* d_in, const int* in_sizes, int n_in,
                              void* d_out, int out_size)
{
    const float* x   = (const float*)d_in[0];
    const int*   src = (const int*)d_in[1];
    const int*   dst = (const int*)d_in[2];
    const float* gcn_w0 = (const float*)d_in[3];
    const float* bn_g0  = (const float*)d_in[5];
    const float* bn_b0  = (const float*)d_in[6];
    const float *sc_w0, *sc_b0, *gcn_w1, *bn_g1, *bn_b1, *gcn_w2, *bn_g2, *bn_b2;
    if (in_sizes[7] == FD * HH) {  // reference-signature order
        sc_w0  = (const float*)d_in[7];
        sc_b0  = (const float*)d_in[8];
        gcn_w1 = (const float*)d_in[9];
        bn_g1  = (const float*)d_in[11];
        bn_b1  = (const float*)d_in[12];
        gcn_w2 = (const float*)d_in[13];
        bn_g2  = (const float*)d_in[15];
        bn_b2  = (const float*)d_in[16];
    } else {                        // setup_inputs dict order
        gcn_w1 = (const float*)d_in[7];
        bn_g1  = (const float*)d_in[9];
        bn_b1  = (const float*)d_in[10];
        gcn_w2 = (const float*)d_in[11];
        bn_g2  = (const float*)d_in[13];
        bn_b2  = (const float*)d_in[14];
        sc_w0  = (const float*)d_in[15];
        sc_b0  = (const float*)d_in[16];
    }
    const float* edge_w = (const float*)d_in[17];
    const float* fd_w0  = (const float*)d_in[18];
    const float* fd_b0  = (const float*)d_in[19];
    const float* fd_g0  = (const float*)d_in[20];
    const float* fd_be0 = (const float*)d_in[21];
    const float* fd_w1  = (const float*)d_in[22];
    const float* fd_b1  = (const float*)d_in[23];
    const float* fd_g1  = (const float*)d_in[24];
    const float* fd_be1 = (const float*)d_in[25];
    const float* fd_w2  = (const float*)d_in[26];
    const float* fd_b2  = (const float*)d_in[27];
    const float* ph_w0  = (const float*)d_in[28];
    const float* ph_b0  = (const float*)d_in[29];
    const float* ph_w1  = (const float*)d_in[30];
    const float* ph_b1  = (const float*)d_in[31];

    float* out = (float*)d_out;
    float* out_z   = out;
    float* out_adj = out + (size_t)NN * HH;
    float* out_xr  = out_adj + (size_t)BB * MAXN * MAXN;
    float* out_zg  = out_xr + (size_t)NN * FD;
    float* out_mlp = out_zg + (size_t)BB * HH;

    float *pA, *pB, *pZ, *pSC;
    cudaGetSymbolAddress((void**)&pA, g_bufA);
    cudaGetSymbolAddress((void**)&pB, g_bufB);
    cudaGetSymbolAddress((void**)&pZ, g_z);
    cudaGetSymbolAddress((void**)&pSC, g_sc);
    __nv_bfloat16 *p0h, *p0l, *p1h, *p1l, *s0h, *s0l, *s1h, *s1l, *wh, *wl;
    cudaGetSymbolAddress((void**)&p0h, g_p0hi);
    cudaGetSymbolAddress((void**)&p0l, g_p0lo);
    cudaGetSymbolAddress((void**)&p1h, g_p1hi);
    cudaGetSymbolAddress((void**)&p1l, g_p1lo);
    cudaGetSymbolAddress((void**)&s0h, g_s0hi);
    cudaGetSymbolAddress((void**)&s0l, g_s0lo);
    cudaGetSymbolAddress((void**)&s1h, g_s1hi);
    cudaGetSymbolAddress((void**)&s1l, g_s1lo);
    cudaGetSymbolAddress((void**)&wh, g_whi);
    cudaGetSymbolAddress((void**)&wl, g_wlo);

    const int SMEM_SZ = 2 * STAGEB;      // 81920
    const int AGG_SMEM = 128 * 128 * 4;  // 65536
    cudaFuncSetAttribute(mma_gemm<false, false>,
                         cudaFuncAttributeMaxDynamicSharedMemorySize, SMEM_SZ);
    cudaFuncSetAttribute(mma_gemm<false, true>,
                         cudaFuncAttributeMaxDynamicSharedMemorySize, SMEM_SZ);
    cudaFuncSetAttribute(mma_gemm<true, false>,
                         cudaFuncAttributeMaxDynamicSharedMemorySize, SMEM_SZ);
    cudaFuncSetAttribute(aggregate,
                         cudaFuncAttributeMaxDynamicSharedMemorySize, AGG_SMEM);

    // ---- graph structure precompute ----
    k_zero_deg<<<NN / 256, 256>>>();
    k_count_deg<<<EE / 256, 256>>>(dst);
    k_scan_rows<<<BB, 128>>>();
    k_fill_csr<<<EE / 256, 256>>>(src, dst);

    // ---- operand conversion ----
    a_conv<<<NN * FD / 1024, 256>>>(x, p0h, p0l, NN * FD / 4);
    WList wlist;
    wlist.w[0] = gcn_w0; wlist.kd[0] = FD; wlist.nd[0] = HH;
    wlist.w[1] = sc_w0;  wlist.kd[1] = FD; wlist.nd[1] = HH;
    wlist.w[2] = gcn_w1; wlist.kd[2] = HH; wlist.nd[2] = HH;
    wlist.w[3] = gcn_w2; wlist.kd[3] = HH; wlist.nd[3] = HH;
    wlist.w[4] = edge_w; wlist.kd[4] = HH; wlist.nd[4] = HH;
    wlist.w[5] = fd_w0;  wlist.kd[5] = HH; wlist.nd[5] = HH;
    wlist.w[6] = fd_w1;  wlist.kd[6] = HH; wlist.nd[6] = HH;
    wlist.w[7] = fd_w2;  wlist.kd[7] = HH; wlist.nd[7] = FD;
    wlist.w[8] = ph_w0;  wlist.kd[8] = HH; wlist.nd[8] = HH;
    wlist.w[9] = ph_w1;  wlist.kd[9] = HH; wlist.nd[9] = HH;
    w_conv_all<<<dim3(256, 10), 256>>>(wlist, wh, wl);

    dim3 gBig(NN / 128, HH / 128);   // (256, 2)
    dim3 gXr(NN / 128, FD / 128);    // (256, 1)
    dim3 gAdj(NN / 128, 1);          // (256, 1)
    dim3 gPh(BB / 128, HH / 128);    // (2, 2)
    const int BA = NN * HH / 1024;   // bn_apply grid (8192)

    // ---- block 0: gcn0 (K=128) + shortcut + bn ----
    mma_gemm<false, false><<<gBig, 256, SMEM_SZ>>>(p0h, p0l, wh + 0 * 65536, wl + 0 * 65536,
                                                   nullptr, pA, nullptr, nullptr, FD, HH, 0);
    mma_gemm<false, false><<<gBig, 256, SMEM_SZ>>>(p0h, p0l, wh + 1 * 65536, wl + 1 * 65536,
                                                   sc_b0, pSC, nullptr, nullptr, FD, HH, 0);
    k_zero_stats<<<1, 512>>>();
    aggregate<<<BB, 256, AGG_SMEM>>>(pA, pB, 1);
    bn_apply<<<BA, 256>>>(pB, pSC, bn_g0, bn_b0, pZ, p0h, p0l, 1);

    // ---- block 1 ----
    mma_gemm<false, false><<<gBig, 256, SMEM_SZ>>>(p0h, p0l, wh + 2 * 65536, wl + 2 * 65536,
                                                   nullptr, pA, nullptr, nullptr, HH, HH, 0);
    k_zero_stats<<<1, 512>>>();
    aggregate<<<BB, 256, AGG_SMEM>>>(pA, pB, 1);
    bn_apply<<<BA, 256>>>(pB, pZ, bn_g1, bn_b1, pZ, p0h, p0l, 1);

    // ---- block 2 ----
    mma_gemm<false, false><<<gBig, 256, SMEM_SZ>>>(p0h, p0l, wh + 3 * 65536, wl + 3 * 65536,
                                                   nullptr, pA, nullptr, nullptr, HH, HH, 0);
    k_zero_stats<<<1, 512>>>();
    aggregate<<<BB, 256, AGG_SMEM>>>(pA, pB, 1);
    bn_apply<<<BA, 256>>>(pB, pZ, bn_g2, bn_b2, pZ, nullptr, nullptr, 1);

    // ---- fused l2 normalize (output 0) + max pool (output 3) + bf16 emits ----
    l2norm_pool<<<BB, 256>>>(pZ, out_z, p0h, p0l, out_zg, s0h, s0l);

    // ---- edge decoder: zw = z @ edge_w (bf16 emit), adj = sigmoid(zw z^T) ----
    mma_gemm<false, false><<<gBig, 256, SMEM_SZ>>>(p0h, p0l, wh + 4 * 65536, wl + 4 * 65536,
                                                   nullptr, nullptr, p1h, p1l, HH, HH, 0);
    mma_gemm<true, false><<<gAdj, 256, SMEM_SZ>>>(p1h, p1l, p0h, p0l,
                                                  nullptr, out_adj, nullptr, nullptr, HH, MAXN, 0);

    // ---- feature decoder (stats fused in GEMM epilogue) ----
    k_zero_stats<<<1, 512>>>();
    mma_gemm<false, true><<<gBig, 256, SMEM_SZ>>>(p0h, p0l, wh + 5 * 65536, wl + 5 * 65536,
                                                  fd_b0, pB, nullptr, nullptr, HH, HH, 1);
    bn_apply<<<BA, 256>>>(pB, nullptr, fd_g0, fd_be0, nullptr, p1h, p1l, 0);
    k_zero_stats<<<1, 512>>>();
    mma_gemm<false, true><<<gBig, 256, SMEM_SZ>>>(p1h, p1l, wh + 6 * 65536, wl + 6 * 65536,
                                                  fd_b1, pB, nullptr, nullptr, HH, HH, 1);
    bn_apply<<<BA, 256>>>(pB, nullptr, fd_g1, fd_be1, nullptr, p0h, p0l, 0);
    mma_gemm<false, false><<<gXr, 256, SMEM_SZ>>>(p0h, p0l, wh + 7 * 65536, wl + 7 * 65536,
                                                  fd_b2, out_xr, nullptr, nullptr, HH, FD, 0);

    // ---- pooling head (z_g already emitted by l2norm_pool) ----
    mma_gemm<false, false><<<gPh, 256, SMEM_SZ>>>(s0h, s0l, wh + 8 * 65536, wl + 8 * 65536,
                                                  ph_b0, nullptr, s1h, s1l, HH, HH, 1);
    mma_gemm<false, false><<<gPh, 256, SMEM_SZ>>>(s1h, s1l, wh + 9 * 65536, wl + 9 * 65536,
                                                  ph_b1, out_mlp, nullptr, nullptr, HH, HH, 0);
}

// round 8
// speedup vs baseline: 1.0992x; 1.0992x over previous
#include <cuda_runtime.h>
#include <cuda_bf16.h>
#include <math.h>
#include <stdint.h>

// Problem constants
#define NN   32768      // nodes
#define HH   256        // hidden
#define FD   128        // input feature dim
#define BB   256        // graphs
#define MAXN 128        // nodes per graph
#define EE   524288     // edges
#define EPG  2048       // edges per graph (EE/BB)

// ======================= PTX helpers (baseline compute_100 only) =======================
__device__ __forceinline__ uint32_t smem_to_u32(const void* smem_ptr) {
    uint32_t addr;
    asm("{ .reg .u64 tmp; cvta.to.shared.u64 tmp, %1; cvt.u32.u64 %0, tmp; }"
        : "=r"(addr) : "l"(smem_ptr));
    return addr;
}
__device__ __forceinline__ void ldsm4(uint32_t* r, uint32_t addr) {
    asm volatile("ldmatrix.sync.aligned.m8n8.x4.shared.b16 {%0,%1,%2,%3}, [%4];"
        : "=r"(r[0]), "=r"(r[1]), "=r"(r[2]), "=r"(r[3]) : "r"(addr));
}
__device__ __forceinline__ void mma16816(float* d, const uint32_t* a, uint32_t b0, uint32_t b1) {
    asm volatile(
        "mma.sync.aligned.m16n8k16.row.col.f32.bf16.bf16.f32 "
        "{%0,%1,%2,%3}, {%4,%5,%6,%7}, {%8,%9}, {%0,%1,%2,%3};"
        : "+f"(d[0]), "+f"(d[1]), "+f"(d[2]), "+f"(d[3])
        : "r"(a[0]), "r"(a[1]), "r"(a[2]), "r"(a[3]), "r"(b0), "r"(b1));
}
__device__ __forceinline__ void cp16(uint32_t s, const void* g) {
    asm volatile("cp.async.cg.shared.global [%0], [%1], 16;" :: "r"(s), "l"(g) : "memory");
}
__device__ __forceinline__ void cp_commit() {
    asm volatile("cp.async.commit_group;" ::: "memory");
}
template<int NG> __device__ __forceinline__ void cp_wait() {
    asm volatile("cp.async.wait_group %0;" :: "n"(NG) : "memory");
}

// ---------------- scratch (device globals) ----------------
__device__ __align__(256) float g_bufA[(size_t)NN * HH];
__device__ __align__(256) float g_bufB[(size_t)NN * HH];
__device__ __align__(256) float g_z[(size_t)NN * HH];
__device__ __align__(256) float g_sc[(size_t)NN * HH];
__device__ float g_dinv[NN];
__device__ int   g_deg[NN];
__device__ int   g_rowstart[NN];
__device__ int   g_cursor[NN];
__device__ int   g_csr_src[EE];
__device__ float g_csr_norm[EE];
__device__ float g_stats[2 * HH];

// bf16 hi/lo operand buffers
__device__ __align__(256) __nv_bfloat16 g_p0hi[(size_t)NN * HH];
__device__ __align__(256) __nv_bfloat16 g_p0lo[(size_t)NN * HH];
__device__ __align__(256) __nv_bfloat16 g_p1hi[(size_t)NN * HH];
__device__ __align__(256) __nv_bfloat16 g_p1lo[(size_t)NN * HH];
__device__ __align__(256) __nv_bfloat16 g_p2hi[(size_t)NN * HH];
__device__ __align__(256) __nv_bfloat16 g_p2lo[(size_t)NN * HH];
__device__ __align__(256) __nv_bfloat16 g_s0hi[BB * HH];
__device__ __align__(256) __nv_bfloat16 g_s0lo[BB * HH];
__device__ __align__(256) __nv_bfloat16 g_s1hi[BB * HH];
__device__ __align__(256) __nv_bfloat16 g_s1lo[BB * HH];
__device__ __align__(256) __nv_bfloat16 g_whi[10 * 65536];  // 10 transposed weights
__device__ __align__(256) __nv_bfloat16 g_wlo[10 * 65536];

// ---------------- precompute: degrees, dinv, CSR ----------------
__global__ void k_count_deg(const int* __restrict__ dst) {
    int e = blockIdx.x * 256 + threadIdx.x;
    if (e >= EE) return;
    int g = e >> 11;
    atomicAdd(&g_deg[g * MAXN + dst[e]], 1);
}
// per-graph CTA: exclusive scan of edge degrees + dinv
__global__ void k_scan_rows() {
    int g = blockIdx.x;
    int t = threadIdx.x;
    int n = g * MAXN + t;
    __shared__ int s[MAXN];
    int d = g_deg[n];
    g_dinv[n] = rsqrtf((float)(d + 1));   // self loop adds 1
    s[t] = d;
    __syncthreads();
    for (int off = 1; off < MAXN; off <<= 1) {
        int v = (t >= off) ? s[t - off] : 0;
        __syncthreads();
        s[t] += v;
        __syncthreads();
    }
    int start = g * EPG + s[t] - d;
    g_rowstart[n] = start;
    g_cursor[n] = start;
}
__global__ void k_fill_csr(const int* __restrict__ src, const int* __restrict__ dst) {
    int e = blockIdx.x * 256 + threadIdx.x;
    if (e >= EE) return;
    int g = e >> 11;
    int s = src[e], d = dst[e];
    int slot = atomicAdd(&g_cursor[g * MAXN + d], 1);
    g_csr_src[slot] = s;
    g_csr_norm[slot] = g_dinv[g * MAXN + s] * g_dinv[g * MAXN + d];
}

// ---------------- fp32 -> bf16 hi/lo converts ----------------
__device__ __forceinline__ void split_bf16(float v, __nv_bfloat16& h, __nv_bfloat16& l) {
    h = __float2bfloat16(v);
    l = __float2bfloat16(v - __bfloat162float(h));
}
__device__ __forceinline__ void emit4(__nv_bfloat16* hi, __nv_bfloat16* lo, size_t o,
                                      float a, float b, float c, float d) {
    __nv_bfloat16 h0, l0, h1, l1, h2, l2, h3, l3;
    split_bf16(a, h0, l0); split_bf16(b, h1, l1);
    split_bf16(c, h2, l2); split_bf16(d, h3, l3);
    __nv_bfloat162 hv0 = {h0, h1}, hv1 = {h2, h3};
    __nv_bfloat162 lv0 = {l0, l1}, lv1 = {l2, l3};
    *(__nv_bfloat162*)(hi + o) = hv0;
    *(__nv_bfloat162*)(hi + o + 2) = hv1;
    *(__nv_bfloat162*)(lo + o) = lv0;
    *(__nv_bfloat162*)(lo + o + 2) = lv1;
}
__global__ void a_conv(const float* __restrict__ A, __nv_bfloat16* __restrict__ hi,
                       __nv_bfloat16* __restrict__ lo, int n4) {
    int i = blockIdx.x * 256 + threadIdx.x;
    if (i >= n4) return;
    float4 v = ((const float4*)A)[i];
    emit4(hi, lo, (size_t)i * 4, v.x, v.y, v.z, v.w);
}
// all 10 weights in one launch: W[K,N] fp32 -> hi/lo[N,K] bf16 at slot w*65536
struct WList { const float* w[10]; int kd[10]; int nd[10]; };
__global__ void w_conv_all(WList wl, __nv_bfloat16* __restrict__ hi,
                           __nv_bfloat16* __restrict__ lo) {
    int widx = blockIdx.y;
    int i = blockIdx.x * 256 + threadIdx.x;
    int Kd = wl.kd[widx], Nd = wl.nd[widx];
    if (i >= Kd * Nd) return;
    int k = i / Nd, n = i - k * Nd;
    __nv_bfloat16 h, l;
    split_bf16(wl.w[widx][i], h, l);
    hi[(size_t)widx * 65536 + (size_t)n * Kd + k] = h;
    lo[(size_t)widx * 65536 + (size_t)n * Kd + k] = l;
}

// ======================= mma.sync split-x3 GEMM =======================
// C[M,Ncols] = A[M,K] @ B[Ncols,K]^T via bf16 hi/lo x3, fp32 accumulate.
// CTA: 128(M) x 128(N) tile, 8 warps (4x2), warp tile 32x64; 2 CTAs/SM.
// K chunks of 32, cp.async double-buffered. SMEM rows padded to 80B.
// STATS: per-column sum/sumsq of the (post-bias/relu) output -> g_stats.
#define ROWB   80
#define MATB   10240            // 128 rows * 80B
#define STAGEB 40960            // 4 matrices (Ahi,Alo,Bhi,Blo)
template<bool ADJ, bool STATS>
__global__ void __launch_bounds__(256, 2)
mma_gemm(const __nv_bfloat16* __restrict__ Ahi, const __nv_bfloat16* __restrict__ Alo,
         const __nv_bfloat16* __restrict__ Bhi, const __nv_bfloat16* __restrict__ Blo,
         const float* __restrict__ bias, float* __restrict__ Cf,
         __nv_bfloat16* __restrict__ Chi, __nv_bfloat16* __restrict__ Clo,
         int K, int Ncols, int relu)
{
    extern __shared__ char smem[];
    const uint32_t sb = smem_to_u32(smem);
    const int tid = threadIdx.x;
    const int lane = tid & 31;
    const int wid = tid >> 5;
    const int warp_m = wid & 3;        // 4 warps along M
    const int warp_n = wid >> 2;       // 2 warps along N
    const int mrow0 = blockIdx.x * 128;
    const int bn0 = blockIdx.y * 128;
    const int brow0 = ADJ ? mrow0 : bn0;

    const __nv_bfloat16* baseA_hi = Ahi + (size_t)mrow0 * K;
    const __nv_bfloat16* baseA_lo = Alo + (size_t)mrow0 * K;
    const __nv_bfloat16* baseB_hi = Bhi + (size_t)brow0 * K;
    const __nv_bfloat16* baseB_lo = Blo + (size_t)brow0 * K;

    float acc[2][8][4];
#pragma unroll
    for (int mt = 0; mt < 2; mt++)
#pragma unroll
        for (int nt = 0; nt < 8; nt++)
#pragma unroll
            for (int v = 0; v < 4; v++) acc[mt][nt][v] = 0.f;

    auto load_chunk = [&](int c, int stage) {
        const int kc = c << 5;
        const uint32_t sbase = sb + stage * STAGEB;
#pragma unroll
        for (int t = 0; t < 8; t++) {
            int i = t * 256 + tid;
            int mat = i >> 9;               // constant per unrolled t
            int r = (i >> 2) & 127;
            int q = i & 3;
            const __nv_bfloat16* g;
            if      (mat == 0) g = baseA_hi + (size_t)r * K + kc + q * 8;
            else if (mat == 1) g = baseA_lo + (size_t)r * K + kc + q * 8;
            else if (mat == 2) g = baseB_hi + (size_t)r * K + kc + q * 8;
            else               g = baseB_lo + (size_t)r * K + kc + q * 8;
            cp16(sbase + mat * MATB + r * ROWB + q * 16, g);
        }
    };

    auto compute_chunk = [&](int stage) {
        const uint32_t sA = sb + stage * STAGEB;
        const uint32_t sB = sA + 2 * MATB;
#pragma unroll
        for (int ks = 0; ks < 2; ks++) {
            const uint32_t koff = ks * 32 + (lane >> 4) * 16;
            uint32_t ahi[2][4], alo[2][4];
#pragma unroll
            for (int mt = 0; mt < 2; mt++) {
                uint32_t ad = sA + (uint32_t)((warp_m * 32 + mt * 16 + (lane & 15)) * ROWB) + koff;
                ldsm4(ahi[mt], ad);
                ldsm4(alo[mt], ad + MATB);
            }
            // B fragments in two halves (register pressure: enables 2 CTAs/SM)
#pragma unroll
            for (int half = 0; half < 2; half++) {
                uint32_t bhiR[2][4], bloR[2][4];
#pragma unroll
                for (int g2 = 0; g2 < 2; g2++) {
                    uint32_t ad = sB + (uint32_t)((warp_n * 64 + (half * 2 + g2) * 16
                                   + (lane & 15)) * ROWB) + koff;
                    ldsm4(bhiR[g2], ad);
                    ldsm4(bloR[g2], ad + MATB);
                }
#pragma unroll
                for (int mt = 0; mt < 2; mt++)
#pragma unroll
                    for (int nt = 0; nt < 4; nt++) {
                        int g2 = nt >> 1, s = nt & 1;
                        float* ac = acc[mt][half * 4 + nt];
                        mma16816(ac, ahi[mt], bhiR[g2][s], bhiR[g2][s + 2]);
                        mma16816(ac, ahi[mt], bloR[g2][s], bloR[g2][s + 2]);
                        mma16816(ac, alo[mt], bhiR[g2][s], bhiR[g2][s + 2]);
                    }
            }
        }
    };

    const int nch = K >> 5;
    load_chunk(0, 0);
    cp_commit();
    for (int c = 0; c < nch; c++) {
        if (c + 1 < nch) {
            load_chunk(c + 1, (c + 1) & 1);
            cp_commit();
            cp_wait<1>();
        } else {
            cp_wait<0>();
        }
        __syncthreads();
        compute_chunk(c & 1);
        __syncthreads();
    }

    // ---- epilogue (register-resident) ----
    float* sst = (float*)smem;   // 256 floats: [0:128) sums, [128:256) sumsq (local cols)
    if (STATS) {
        if (tid < 256) sst[tid] = 0.f;
        __syncthreads();
    }
    float colsum[16], colsq[16];
    if (STATS) {
#pragma unroll
        for (int k = 0; k < 16; k++) { colsum[k] = 0.f; colsq[k] = 0.f; }
    }
    const int r0 = lane >> 2;
    const int cq = (lane & 3) * 2;
#pragma unroll
    for (int mt = 0; mt < 2; mt++) {
#pragma unroll
        for (int nt = 0; nt < 8; nt++) {
            int col = bn0 + warp_n * 64 + nt * 8 + cq;
            float bv0 = 0.f, bv1 = 0.f;
            if (bias) { bv0 = bias[col]; bv1 = bias[col + 1]; }
#pragma unroll
            for (int h = 0; h < 2; h++) {
                int row = mrow0 + warp_m * 32 + mt * 16 + r0 + h * 8;
                float v0 = acc[mt][nt][h * 2 + 0] + bv0;
                float v1 = acc[mt][nt][h * 2 + 1] + bv1;
                if (relu) { v0 = fmaxf(v0, 0.f); v1 = fmaxf(v1, 0.f); }
                if (STATS) {
                    colsum[nt * 2] += v0;     colsq[nt * 2] = fmaf(v0, v0, colsq[nt * 2]);
                    colsum[nt * 2 + 1] += v1; colsq[nt * 2 + 1] = fmaf(v1, v1, colsq[nt * 2 + 1]);
                }
                if (ADJ) {
                    v0 = 1.f / (1.f + __expf(-v0));
                    v1 = 1.f / (1.f + __expf(-v1));
                    int rl = row - mrow0;
                    int cl = col;
                    if (rl == cl) v0 = 0.f;
                    if (rl == cl + 1) v1 = 0.f;
                    *(float2*)(Cf + (size_t)blockIdx.x * (MAXN * MAXN)
                               + (size_t)rl * MAXN + cl) = make_float2(v0, v1);
                } else {
                    size_t o = (size_t)row * Ncols + col;
                    if (Cf) *(float2*)(Cf + o) = make_float2(v0, v1);
                    if (Chi) {
                        __nv_bfloat16 h0, l0, h1, l1;
                        split_bf16(v0, h0, l0);
                        split_bf16(v1, h1, l1);
                        __nv_bfloat162 ph = {h0, h1}, pl = {l0, l1};
                        *(__nv_bfloat162*)(Chi + o) = ph;
                        *(__nv_bfloat162*)(Clo + o) = pl;
                    }
                }
            }
        }
    }
    if (STATS) {
#pragma unroll
        for (int nt = 0; nt < 8; nt++) {
            int cl = warp_n * 64 + nt * 8 + cq;
            atomicAdd(&sst[cl],           colsum[nt * 2]);
            atomicAdd(&sst[cl + 1],       colsum[nt * 2 + 1]);
            atomicAdd(&sst[128 + cl],     colsq[nt * 2]);
            atomicAdd(&sst[128 + cl + 1], colsq[nt * 2 + 1]);
        }
        __syncthreads();
        if (tid < 128) {
            atomicAdd(&g_stats[bn0 + tid], sst[tid]);
            atomicAdd(&g_stats[256 + bn0 + tid], sst[128 + tid]);
        }
    }
}

// ---------------- per-graph GCN aggregation + fused BN stats ----------------
__global__ void __launch_bounds__(256)
aggregate(const float* __restrict__ hw, float* __restrict__ outp, int do_stats) {
    extern __shared__ float sh[];           // 128 x 128 fp32 (64KB)
    __shared__ float sstat[512];
    int g = blockIdx.x;
    int tid = threadIdx.x;
    int lane = tid & 31;
    int w = tid >> 5;
    int nbase = g * MAXN;
    if (do_stats) { sstat[tid] = 0.f; sstat[tid + 256] = 0.f; }
    for (int q = 0; q < 2; q++) {
        __syncthreads();
        int c0 = q * 128;
        for (int i = tid; i < 128 * 32; i += 256) {
            ((float4*)sh)[i] =
                *(const float4*)(hw + (size_t)(nbase + (i >> 5)) * HH + c0 + (i & 31) * 4);
        }
        __syncthreads();
        float ps0 = 0.f, ps1 = 0.f, ps2 = 0.f, ps3 = 0.f;
        float pq0 = 0.f, pq1 = 0.f, pq2 = 0.f, pq3 = 0.f;
        for (int n = w; n < MAXN; n += 8) {
            int gn = nbase + n;
            int rs = g_rowstart[gn];
            int cnt = g_deg[gn];
            float di = g_dinv[gn];
            float sl = di * di;
            float4 self = *(const float4*)&sh[n * 128 + lane * 4];
            float a0 = self.x * sl, a1 = self.y * sl, a2 = self.z * sl, a3 = self.w * sl;
            for (int e = 0; e < cnt; e++) {
                int s = __ldg(&g_csr_src[rs + e]);
                float nm = __ldg(&g_csr_norm[rs + e]);
                float4 p = *(const float4*)&sh[s * 128 + lane * 4];
                a0 = fmaf(p.x, nm, a0);
                a1 = fmaf(p.y, nm, a1);
                a2 = fmaf(p.z, nm, a2);
                a3 = fmaf(p.w, nm, a3);
            }
            *(float4*)(outp + (size_t)gn * HH + c0 + lane * 4) = make_float4(a0, a1, a2, a3);
            if (do_stats) {
                ps0 += a0; ps1 += a1; ps2 += a2; ps3 += a3;
                pq0 = fmaf(a0, a0, pq0); pq1 = fmaf(a1, a1, pq1);
                pq2 = fmaf(a2, a2, pq2); pq3 = fmaf(a3, a3, pq3);
            }
        }
        if (do_stats) {
            int c = c0 + lane * 4;
            atomicAdd(&sstat[c + 0], ps0); atomicAdd(&sstat[c + 1], ps1);
            atomicAdd(&sstat[c + 2], ps2); atomicAdd(&sstat[c + 3], ps3);
            atomicAdd(&sstat[256 + c + 0], pq0); atomicAdd(&sstat[256 + c + 1], pq1);
            atomicAdd(&sstat[256 + c + 2], pq2); atomicAdd(&sstat[256 + c + 3], pq3);
        }
    }
    if (do_stats) {
        __syncthreads();
        atomicAdd(&g_stats[tid], sstat[tid]);
        atomicAdd(&g_stats[tid + 256], sstat[tid + 256]);
    }
}

// ---------------- BatchNorm apply (vectorized, + bf16 emit) ----------------
// mode 0: out = bn(x); mode 1: out = relu(relu(bn(x)) + res). float4 per thread.
__global__ void bn_apply(const float* __restrict__ xin, const float* __restrict__ res,
                         const float* __restrict__ gam, const float* __restrict__ bet,
                         float* __restrict__ outp,
                         __nv_bfloat16* __restrict__ ohi, __nv_bfloat16* __restrict__ olo,
                         int mode)
{
    size_t i4 = ((size_t)blockIdx.x * 256 + threadIdx.x) * 4;
    int col = (int)(i4 & 255);
    const float invN = 1.0f / (float)NN;
    float a[4], bp[4];
#pragma unroll
    for (int k = 0; k < 4; k++) {
        float m = g_stats[col + k] * invN;
        float var = fmaxf(g_stats[HH + col + k] * invN - m * m, 0.f);
        float aa = gam[col + k] * rsqrtf(var + 1e-5f);
        a[k] = aa;
        bp[k] = bet[col + k] - m * aa;
    }
    float4 xv = *(const float4*)(xin + i4);
    float v[4] = { fmaf(xv.x, a[0], bp[0]), fmaf(xv.y, a[1], bp[1]),
                   fmaf(xv.z, a[2], bp[2]), fmaf(xv.w, a[3], bp[3]) };
    if (mode == 1) {
        float4 rv = *(const float4*)(res + i4);
        v[0] = fmaxf(fmaxf(v[0], 0.f) + rv.x, 0.f);
        v[1] = fmaxf(fmaxf(v[1], 0.f) + rv.y, 0.f);
        v[2] = fmaxf(fmaxf(v[2], 0.f) + rv.z, 0.f);
        v[3] = fmaxf(fmaxf(v[3], 0.f) + rv.w, 0.f);
    }
    if (outp) *(float4*)(outp + i4) = make_float4(v[0], v[1], v[2], v[3]);
    if (ohi) emit4(ohi, olo, i4, v[0], v[1], v[2], v[3]);
}

// ---------------- fused row L2 normalize + per-graph max pool ----------------
__global__ void __launch_bounds__(256)
l2norm_pool(const float* __restrict__ zin, float* __restrict__ out_z,
            __nv_bfloat16* __restrict__ ohi, __nv_bfloat16* __restrict__ olo,
            float* __restrict__ out_zg,
            __nv_bfloat16* __restrict__ shi, __nv_bfloat16* __restrict__ slo)
{
    __shared__ float rinv[MAXN];
    int g = blockIdx.x;
    int tid = threadIdx.x;
    int lane = tid & 31;
    int w = tid >> 5;
    const float* base = zin + (size_t)g * MAXN * HH;
    for (int r = w; r < MAXN; r += 8) {
        const float4* p = (const float4*)(base + (size_t)r * HH);
        float4 v0 = p[lane], v1 = p[lane + 32];
        float s = v0.x * v0.x + v0.y * v0.y + v0.z * v0.z + v0.w * v0.w
                + v1.x * v1.x + v1.y * v1.y + v1.z * v1.z + v1.w * v1.w;
#pragma unroll
        for (int o = 16; o > 0; o >>= 1) s += __shfl_xor_sync(0xffffffffu, s, o);
        if (lane == 0) rinv[r] = 1.f / fmaxf(sqrtf(s), 1e-12f);
    }
    __syncthreads();
    int c = tid;                       // 256 cols, one per thread
    float mx = -1e30f;
    for (int r = 0; r < MAXN; r++) {
        float v = base[(size_t)r * HH + c] * rinv[r];
        mx = fmaxf(mx, v);
        size_t o = (size_t)(g * MAXN + r) * HH + c;
        out_z[o] = v;
        __nv_bfloat16 h, l;
        split_bf16(v, h, l);
        ohi[o] = h; olo[o] = l;
    }
    int o2 = g * HH + c;
    out_zg[o2] = mx;
    __nv_bfloat16 h, l;
    split_bf16(mx, h, l);
    shi[o2] = h; slo[o2] = l;
}

// ---------------- launcher ----------------
extern "C" void kernel_launch(void* const* d_in, const int* in_sizes, int n_in,
                              void* d_out, int out_size)
{
    const float* x   = (const float*)d_in[0];
    const int*   src = (const int*)d_in[1];
    const int*   dst = (const int*)d_in[2];
    const float* gcn_w0 = (const float*)d_in[3];
    const float* bn_g0  = (const float*)d_in[5];
    const float* bn_b0  = (const float*)d_in[6];
    const float *sc_w0, *sc_b0, *gcn_w1, *bn_g1, *bn_b1, *gcn_w2, *bn_g2, *bn_b2;
    if (in_sizes[7] == FD * HH) {  // reference-signature order
        sc_w0  = (const float*)d_in[7];
        sc_b0  = (const float*)d_in[8];
        gcn_w1 = (const float*)d_in[9];
        bn_g1  = (const float*)d_in[11];
        bn_b1  = (const float*)d_in[12];
        gcn_w2 = (const float*)d_in[13];
        bn_g2  = (const float*)d_in[15];
        bn_b2  = (const float*)d_in[16];
    } else {                        // setup_inputs dict order
        gcn_w1 = (const float*)d_in[7];
        bn_g1  = (const float*)d_in[9];
        bn_b1  = (const float*)d_in[10];
        gcn_w2 = (const float*)d_in[11];
        bn_g2  = (const float*)d_in[13];
        bn_b2  = (const float*)d_in[14];
        sc_w0  = (const float*)d_in[15];
        sc_b0  = (const float*)d_in[16];
    }
    const float* edge_w = (const float*)d_in[17];
    const float* fd_w0  = (const float*)d_in[18];
    const float* fd_b0  = (const float*)d_in[19];
    const float* fd_g0  = (const float*)d_in[20];
    const float* fd_be0 = (const float*)d_in[21];
    const float* fd_w1  = (const float*)d_in[22];
    const float* fd_b1  = (const float*)d_in[23];
    const float* fd_g1  = (const float*)d_in[24];
    const float* fd_be1 = (const float*)d_in[25];
    const float* fd_w2  = (const float*)d_in[26];
    const float* fd_b2  = (const float*)d_in[27];
    const float* ph_w0  = (const float*)d_in[28];
    const float* ph_b0  = (const float*)d_in[29];
    const float* ph_w1  = (const float*)d_in[30];
    const float* ph_b1  = (const float*)d_in[31];

    float* out = (float*)d_out;
    float* out_z   = out;
    float* out_adj = out + (size_t)NN * HH;
    float* out_xr  = out_adj + (size_t)BB * MAXN * MAXN;
    float* out_zg  = out_xr + (size_t)NN * FD;
    float* out_mlp = out_zg + (size_t)BB * HH;

    float *pA, *pB, *pZ, *pSC, *pStats, *pDinv;
    int *pDeg;
    cudaGetSymbolAddress((void**)&pA, g_bufA);
    cudaGetSymbolAddress((void**)&pB, g_bufB);
    cudaGetSymbolAddress((void**)&pZ, g_z);
    cudaGetSymbolAddress((void**)&pSC, g_sc);
    cudaGetSymbolAddress((void**)&pStats, g_stats);
    cudaGetSymbolAddress((void**)&pDinv, g_dinv);
    cudaGetSymbolAddress((void**)&pDeg, g_deg);
    __nv_bfloat16 *p0h, *p0l, *p1h, *p1l, *p2h, *p2l, *s0h, *s0l, *s1h, *s1l, *wh, *wl;
    cudaGetSymbolAddress((void**)&p0h, g_p0hi);
    cudaGetSymbolAddress((void**)&p0l, g_p0lo);
    cudaGetSymbolAddress((void**)&p1h, g_p1hi);
    cudaGetSymbolAddress((void**)&p1l, g_p1lo);
    cudaGetSymbolAddress((void**)&p2h, g_p2hi);
    cudaGetSymbolAddress((void**)&p2l, g_p2lo);
    cudaGetSymbolAddress((void**)&s0h, g_s0hi);
    cudaGetSymbolAddress((void**)&s0l, g_s0lo);
    cudaGetSymbolAddress((void**)&s1h, g_s1hi);
    cudaGetSymbolAddress((void**)&s1l, g_s1lo);
    cudaGetSymbolAddress((void**)&wh, g_whi);
    cudaGetSymbolAddress((void**)&wl, g_wlo);

    const int SMEM_SZ = 2 * STAGEB;      // 81920
    const int AGG_SMEM = 128 * 128 * 4;  // 65536
    cudaFuncSetAttribute(mma_gemm<false, false>,
                         cudaFuncAttributeMaxDynamicSharedMemorySize, SMEM_SZ);
    cudaFuncSetAttribute(mma_gemm<false, true>,
                         cudaFuncAttributeMaxDynamicSharedMemorySize, SMEM_SZ);
    cudaFuncSetAttribute(mma_gemm<true, false>,
                         cudaFuncAttributeMaxDynamicSharedMemorySize, SMEM_SZ);
    cudaFuncSetAttribute(aggregate,
                         cudaFuncAttributeMaxDynamicSharedMemorySize, AGG_SMEM);

    // ---- static side streams + events (host resources; created once, on the
    //      uncaptured correctness call) ----
    static cudaStream_t sA = nullptr, sBst = nullptr;
    static cudaEvent_t ev[8];
    if (!sA) {
        cudaStreamCreateWithFlags(&sA, cudaStreamNonBlocking);
        cudaStreamCreateWithFlags(&sBst, cudaStreamNonBlocking);
        for (int i = 0; i < 8; i++)
            cudaEventCreateWithFlags(&ev[i], cudaEventDisableTiming);
    }

    dim3 gBig(NN / 128, HH / 128);   // (256, 2)
    dim3 gXr(NN / 128, FD / 128);    // (256, 1)
    dim3 gAdj(NN / 128, 1);          // (256, 1)
    dim3 gPh(BB / 128, HH / 128);    // (2, 2)
    const int BA = NN * HH / 1024;   // bn_apply grid (8192)

    // ================= phase 1: convs (main) || CSR precompute (sA) ==========
    cudaEventRecord(ev[0], 0);
    cudaStreamWaitEvent(sA, ev[0], 0);
    cudaMemsetAsync(pDeg, 0, NN * sizeof(int), sA);
    k_count_deg<<<EE / 256, 256, 0, sA>>>(dst);
    k_scan_rows<<<BB, 128, 0, sA>>>();
    k_fill_csr<<<EE / 256, 256, 0, sA>>>(src, dst);
    cudaEventRecord(ev[1], sA);               // CSR ready

    a_conv<<<NN * FD / 1024, 256>>>(x, p0h, p0l, NN * FD / 4);
    WList wlist;
    wlist.w[0] = gcn_w0; wlist.kd[0] = FD; wlist.nd[0] = HH;
    wlist.w[1] = sc_w0;  wlist.kd[1] = FD; wlist.nd[1] = HH;
    wlist.w[2] = gcn_w1; wlist.kd[2] = HH; wlist.nd[2] = HH;
    wlist.w[3] = gcn_w2; wlist.kd[3] = HH; wlist.nd[3] = HH;
    wlist.w[4] = edge_w; wlist.kd[4] = HH; wlist.nd[4] = HH;
    wlist.w[5] = fd_w0;  wlist.kd[5] = HH; wlist.nd[5] = HH;
    wlist.w[6] = fd_w1;  wlist.kd[6] = HH; wlist.nd[6] = HH;
    wlist.w[7] = fd_w2;  wlist.kd[7] = HH; wlist.nd[7] = FD;
    wlist.w[8] = ph_w0;  wlist.kd[8] = HH; wlist.nd[8] = HH;
    wlist.w[9] = ph_w1;  wlist.kd[9] = HH; wlist.nd[9] = HH;
    w_conv_all<<<dim3(256, 10), 256>>>(wlist, wh, wl);
    cudaEventRecord(ev[2], 0);                // convs ready

    // sc0 GEMM on sBst, concurrent with gcn0 GEMM on main
    cudaStreamWaitEvent(sBst, ev[2], 0);
    mma_gemm<false, false><<<gBig, 256, SMEM_SZ, sBst>>>(p0h, p0l, wh + 1 * 65536, wl + 1 * 65536,
                                                         sc_b0, pSC, nullptr, nullptr, FD, HH, 0);
    cudaEventRecord(ev[3], sBst);             // shortcut ready

    // ---- block 0 ----
    mma_gemm<false, false><<<gBig, 256, SMEM_SZ>>>(p0h, p0l, wh + 0 * 65536, wl + 0 * 65536,
                                                   nullptr, pA, nullptr, nullptr, FD, HH, 0);
    cudaMemsetAsync(pStats, 0, 2 * HH * sizeof(float), 0);
    cudaStreamWaitEvent(0, ev[1], 0);         // need CSR
    aggregate<<<BB, 256, AGG_SMEM>>>(pA, pB, 1);
    cudaStreamWaitEvent(0, ev[3], 0);         // need shortcut
    bn_apply<<<BA, 256>>>(pB, pSC, bn_g0, bn_b0, pZ, p0h, p0l, 1);

    // ---- block 1 ----
    mma_gemm<false, false><<<gBig, 256, SMEM_SZ>>>(p0h, p0l, wh + 2 * 65536, wl + 2 * 65536,
                                                   nullptr, pA, nullptr, nullptr, HH, HH, 0);
    cudaMemsetAsync(pStats, 0, 2 * HH * sizeof(float), 0);
    aggregate<<<BB, 256, AGG_SMEM>>>(pA, pB, 1);
    bn_apply<<<BA, 256>>>(pB, pZ, bn_g1, bn_b1, pZ, p0h, p0l, 1);

    // ---- block 2 ----
    mma_gemm<false, false><<<gBig, 256, SMEM_SZ>>>(p0h, p0l, wh + 3 * 65536, wl + 3 * 65536,
                                                   nullptr, pA, nullptr, nullptr, HH, HH, 0);
    cudaMemsetAsync(pStats, 0, 2 * HH * sizeof(float), 0);
    aggregate<<<BB, 256, AGG_SMEM>>>(pA, pB, 1);
    bn_apply<<<BA, 256>>>(pB, pZ, bn_g2, bn_b2, pZ, nullptr, nullptr, 1);

    // ---- fused l2 normalize (output 0) + max pool (output 3) ----
    l2norm_pool<<<BB, 256>>>(pZ, out_z, p0h, p0l, out_zg, s0h, s0l);
    cudaEventRecord(ev[4], 0);                // z (fp32 + bf16) + z_g ready

    // ================= phase 2: three independent decoder chains =============
    // sA: edge decoder -> out_adj
    cudaStreamWaitEvent(sA, ev[4], 0);
    mma_gemm<false, false><<<gBig, 256, SMEM_SZ, sA>>>(p0h, p0l, wh + 4 * 65536, wl + 4 * 65536,
                                                       nullptr, nullptr, p1h, p1l, HH, HH, 0);
    mma_gemm<true, false><<<gAdj, 256, SMEM_SZ, sA>>>(p1h, p1l, p0h, p0l,
                                                      nullptr, out_adj, nullptr, nullptr, HH, MAXN, 0);
    cudaEventRecord(ev[5], sA);

    // sBst: pooling head -> out_mlp
    cudaStreamWaitEvent(sBst, ev[4], 0);
    mma_gemm<false, false><<<gPh, 256, SMEM_SZ, sBst>>>(s0h, s0l, wh + 8 * 65536, wl + 8 * 65536,
                                                        ph_b0, nullptr, s1h, s1l, HH, HH, 1);
    mma_gemm<false, false><<<gPh, 256, SMEM_SZ, sBst>>>(s1h, s1l, wh + 9 * 65536, wl + 9 * 65536,
                                                        ph_b1, out_mlp, nullptr, nullptr, HH, HH, 0);
    cudaEventRecord(ev[6], sBst);

    // main: feature decoder -> out_xr (uses p2 buffers; p0/p1 untouched)
    cudaMemsetAsync(pStats, 0, 2 * HH * sizeof(float), 0);
    mma_gemm<false, true><<<gBig, 256, SMEM_SZ>>>(p0h, p0l, wh + 5 * 65536, wl + 5 * 65536,
                                                  fd_b0, pB, nullptr, nullptr, HH, HH, 1);
    bn_apply<<<BA, 256>>>(pB, nullptr, fd_g0, fd_be0, nullptr, p2h, p2l, 0);
    cudaMemsetAsync(pStats, 0, 2 * HH * sizeof(float), 0);
    mma_gemm<false, true><<<gBig, 256, SMEM_SZ>>>(p2h, p2l, wh + 6 * 65536, wl + 6 * 65536,
                                                  fd_b1, pB, nullptr, nullptr, HH, HH, 1);
    bn_apply<<<BA, 256>>>(pB, nullptr, fd_g1, fd_be1, nullptr, p2h, p2l, 0);
    mma_gemm<false, false><<<gXr, 256, SMEM_SZ>>>(p2h, p2l, wh + 7 * 65536, wl + 7 * 65536,
                                                  fd_b2, out_xr, nullptr, nullptr, HH, FD, 0);

    // join side streams back into the capture-origin stream
    cudaStreamWaitEvent(0, ev[5], 0);
    cudaStreamWaitEvent(0, ev[6], 0);
}

// round 9
// speedup vs baseline: 1.1478x; 1.0442x over previous
#include <cuda_runtime.h>
#include <cuda_bf16.h>
#include <math.h>
#include <stdint.h>

// Problem constants
#define NN   32768      // nodes
#define HH   256        // hidden
#define FD   128        // input feature dim
#define BB   256        // graphs
#define MAXN 128        // nodes per graph
#define EE   524288     // edges
#define EPG  2048       // edges per graph (EE/BB)

// ======================= PTX helpers (baseline compute_100 only) =======================
__device__ __forceinline__ uint32_t smem_to_u32(const void* smem_ptr) {
    uint32_t addr;
    asm("{ .reg .u64 tmp; cvta.to.shared.u64 tmp, %1; cvt.u32.u64 %0, tmp; }"
        : "=r"(addr) : "l"(smem_ptr));
    return addr;
}
__device__ __forceinline__ void ldsm4(uint32_t* r, uint32_t addr) {
    asm volatile("ldmatrix.sync.aligned.m8n8.x4.shared.b16 {%0,%1,%2,%3}, [%4];"
        : "=r"(r[0]), "=r"(r[1]), "=r"(r[2]), "=r"(r[3]) : "r"(addr));
}
__device__ __forceinline__ void mma16816(float* d, const uint32_t* a, uint32_t b0, uint32_t b1) {
    asm volatile(
        "mma.sync.aligned.m16n8k16.row.col.f32.bf16.bf16.f32 "
        "{%0,%1,%2,%3}, {%4,%5,%6,%7}, {%8,%9}, {%0,%1,%2,%3};"
        : "+f"(d[0]), "+f"(d[1]), "+f"(d[2]), "+f"(d[3])
        : "r"(a[0]), "r"(a[1]), "r"(a[2]), "r"(a[3]), "r"(b0), "r"(b1));
}
__device__ __forceinline__ void cp16(uint32_t s, const void* g) {
    asm volatile("cp.async.cg.shared.global [%0], [%1], 16;" :: "r"(s), "l"(g) : "memory");
}
__device__ __forceinline__ void cp_commit() {
    asm volatile("cp.async.commit_group;" ::: "memory");
}
template<int NG> __device__ __forceinline__ void cp_wait() {
    asm volatile("cp.async.wait_group %0;" :: "n"(NG) : "memory");
}

// ---------------- scratch (device globals) ----------------
__device__ __align__(256) float g_bufA[(size_t)NN * HH];
__device__ __align__(256) float g_bufB[(size_t)NN * HH];
__device__ __align__(256) float g_z[(size_t)NN * HH];
__device__ __align__(256) float g_sc[(size_t)NN * HH];
__device__ float g_dinv[NN];
__device__ int   g_deg[NN];
__device__ int   g_rowstart[NN];
__device__ int   g_cursor[NN];
__device__ int   g_csr_src[EE];
__device__ float g_csr_norm[EE];
__device__ float g_stats[2 * HH];
__device__ unsigned int g_bar;
__device__ float g_bfold[HH];

// bf16 hi/lo operand buffers
__device__ __align__(256) __nv_bfloat16 g_p0hi[(size_t)NN * HH];
__device__ __align__(256) __nv_bfloat16 g_p0lo[(size_t)NN * HH];
__device__ __align__(256) __nv_bfloat16 g_p1hi[(size_t)NN * HH];
__device__ __align__(256) __nv_bfloat16 g_p1lo[(size_t)NN * HH];
__device__ __align__(256) __nv_bfloat16 g_p2hi[(size_t)NN * HH];
__device__ __align__(256) __nv_bfloat16 g_p2lo[(size_t)NN * HH];
__device__ __align__(256) __nv_bfloat16 g_p3hi[(size_t)NN * HH];
__device__ __align__(256) __nv_bfloat16 g_p3lo[(size_t)NN * HH];
__device__ __align__(256) __nv_bfloat16 g_s0hi[BB * HH];
__device__ __align__(256) __nv_bfloat16 g_s0lo[BB * HH];
__device__ __align__(256) __nv_bfloat16 g_s1hi[BB * HH];
__device__ __align__(256) __nv_bfloat16 g_s1lo[BB * HH];
__device__ __align__(256) __nv_bfloat16 g_whi[10 * 65536];  // 10 transposed weights
__device__ __align__(256) __nv_bfloat16 g_wlo[10 * 65536];
__device__ __align__(256) __nv_bfloat16 g_wfhi[65536];      // folded weight scratch
__device__ __align__(256) __nv_bfloat16 g_wflo[65536];

// ---------------- precompute: degrees, dinv, CSR ----------------
__global__ void k_count_deg(const int* __restrict__ dst) {
    int e = blockIdx.x * 256 + threadIdx.x;
    if (e >= EE) return;
    int g = e >> 11;
    atomicAdd(&g_deg[g * MAXN + dst[e]], 1);
}
__global__ void k_scan_rows() {
    int g = blockIdx.x;
    int t = threadIdx.x;
    int n = g * MAXN + t;
    __shared__ int s[MAXN];
    int d = g_deg[n];
    g_dinv[n] = rsqrtf((float)(d + 1));   // self loop adds 1
    s[t] = d;
    __syncthreads();
    for (int off = 1; off < MAXN; off <<= 1) {
        int v = (t >= off) ? s[t - off] : 0;
        __syncthreads();
        s[t] += v;
        __syncthreads();
    }
    int start = g * EPG + s[t] - d;
    g_rowstart[n] = start;
    g_cursor[n] = start;
}
__global__ void k_fill_csr(const int* __restrict__ src, const int* __restrict__ dst) {
    int e = blockIdx.x * 256 + threadIdx.x;
    if (e >= EE) return;
    int g = e >> 11;
    int s = src[e], d = dst[e];
    int slot = atomicAdd(&g_cursor[g * MAXN + d], 1);
    g_csr_src[slot] = s;
    g_csr_norm[slot] = g_dinv[g * MAXN + s] * g_dinv[g * MAXN + d];
}

// ---------------- fp32 -> bf16 hi/lo converts ----------------
__device__ __forceinline__ void split_bf16(float v, __nv_bfloat16& h, __nv_bfloat16& l) {
    h = __float2bfloat16(v);
    l = __float2bfloat16(v - __bfloat162float(h));
}
__device__ __forceinline__ void emit4(__nv_bfloat16* hi, __nv_bfloat16* lo, size_t o,
                                      float a, float b, float c, float d) {
    __nv_bfloat16 h0, l0, h1, l1, h2, l2, h3, l3;
    split_bf16(a, h0, l0); split_bf16(b, h1, l1);
    split_bf16(c, h2, l2); split_bf16(d, h3, l3);
    __nv_bfloat162 hv0 = {h0, h1}, hv1 = {h2, h3};
    __nv_bfloat162 lv0 = {l0, l1}, lv1 = {l2, l3};
    *(__nv_bfloat162*)(hi + o) = hv0;
    *(__nv_bfloat162*)(hi + o + 2) = hv1;
    *(__nv_bfloat162*)(lo + o) = lv0;
    *(__nv_bfloat162*)(lo + o + 2) = lv1;
}
__global__ void a_conv(const float* __restrict__ A, __nv_bfloat16* __restrict__ hi,
                       __nv_bfloat16* __restrict__ lo, int n4) {
    int i = blockIdx.x * 256 + threadIdx.x;
    if (i >= n4) return;
    float4 v = ((const float4*)A)[i];
    emit4(hi, lo, (size_t)i * 4, v.x, v.y, v.z, v.w);
}
struct WList { const float* w[10]; int kd[10]; int nd[10]; };
__global__ void w_conv_all(WList wl, __nv_bfloat16* __restrict__ hi,
                           __nv_bfloat16* __restrict__ lo) {
    int widx = blockIdx.y;
    int i = blockIdx.x * 256 + threadIdx.x;
    int Kd = wl.kd[widx], Nd = wl.nd[widx];
    if (i >= Kd * Nd) return;
    int k = i / Nd, n = i - k * Nd;
    __nv_bfloat16 h, l;
    split_bf16(wl.w[widx][i], h, l);
    hi[(size_t)widx * 65536 + (size_t)n * Kd + k] = h;
    lo[(size_t)widx * 65536 + (size_t)n * Kd + k] = l;
}

// ---- fold BN affine into next GEMM weights: W'_jk = a_j W_jk, b'_k = b_k + sum_j bp_j W_jk
// W fp32 [256, Nd]; out whi/wlo [Nd, 256] (K-major operand), bias_out[Nd]. Grid Nd x 256.
__global__ void fold_bn_w(const float* __restrict__ W, const float* __restrict__ bias_in,
                          const float* __restrict__ gam, const float* __restrict__ bet,
                          __nv_bfloat16* __restrict__ whi, __nv_bfloat16* __restrict__ wlo,
                          float* __restrict__ bias_out, int Nd)
{
    __shared__ float red[256];
    int k = blockIdx.x;
    int j = threadIdx.x;
    const float invN = 1.0f / (float)NN;
    float m = g_stats[j] * invN;
    float var = fmaxf(g_stats[256 + j] * invN - m * m, 0.f);
    float a = gam[j] * rsqrtf(var + 1e-5f);
    float bp = bet[j] - m * a;
    float w = W[j * Nd + k];
    __nv_bfloat16 h, l;
    split_bf16(a * w, h, l);
    whi[(size_t)k * 256 + j] = h;
    wlo[(size_t)k * 256 + j] = l;
    red[j] = bp * w;
    __syncthreads();
    for (int o = 128; o > 0; o >>= 1) {
        if (j < o) red[j] += red[j + o];
        __syncthreads();
    }
    if (j == 0) bias_out[k] = bias_in[k] + red[0];
}

// ======================= mma.sync split-x3 GEMM =======================
#define ROWB   80
#define MATB   10240            // 128 rows * 80B
#define STAGEB 40960            // 4 matrices (Ahi,Alo,Bhi,Blo)
template<bool ADJ, bool STATS>
__global__ void __launch_bounds__(256, 2)
mma_gemm(const __nv_bfloat16* __restrict__ Ahi, const __nv_bfloat16* __restrict__ Alo,
         const __nv_bfloat16* __restrict__ Bhi, const __nv_bfloat16* __restrict__ Blo,
         const float* __restrict__ bias, float* __restrict__ Cf,
         __nv_bfloat16* __restrict__ Chi, __nv_bfloat16* __restrict__ Clo,
         int K, int Ncols, int relu)
{
    extern __shared__ char smem[];
    const uint32_t sb = smem_to_u32(smem);
    const int tid = threadIdx.x;
    const int lane = tid & 31;
    const int wid = tid >> 5;
    const int warp_m = wid & 3;
    const int warp_n = wid >> 2;
    const int mrow0 = blockIdx.x * 128;
    const int bn0 = blockIdx.y * 128;
    const int brow0 = ADJ ? mrow0 : bn0;

    const __nv_bfloat16* baseA_hi = Ahi + (size_t)mrow0 * K;
    const __nv_bfloat16* baseA_lo = Alo + (size_t)mrow0 * K;
    const __nv_bfloat16* baseB_hi = Bhi + (size_t)brow0 * K;
    const __nv_bfloat16* baseB_lo = Blo + (size_t)brow0 * K;

    float acc[2][8][4];
#pragma unroll
    for (int mt = 0; mt < 2; mt++)
#pragma unroll
        for (int nt = 0; nt < 8; nt++)
#pragma unroll
            for (int v = 0; v < 4; v++) acc[mt][nt][v] = 0.f;

    auto load_chunk = [&](int c, int stage) {
        const int kc = c << 5;
        const uint32_t sbase = sb + stage * STAGEB;
#pragma unroll
        for (int t = 0; t < 8; t++) {
            int i = t * 256 + tid;
            int mat = i >> 9;
            int r = (i >> 2) & 127;
            int q = i & 3;
            const __nv_bfloat16* g;
            if      (mat == 0) g = baseA_hi + (size_t)r * K + kc + q * 8;
            else if (mat == 1) g = baseA_lo + (size_t)r * K + kc + q * 8;
            else if (mat == 2) g = baseB_hi + (size_t)r * K + kc + q * 8;
            else               g = baseB_lo + (size_t)r * K + kc + q * 8;
            cp16(sbase + mat * MATB + r * ROWB + q * 16, g);
        }
    };

    auto compute_chunk = [&](int stage) {
        const uint32_t sA = sb + stage * STAGEB;
        const uint32_t sB = sA + 2 * MATB;
#pragma unroll
        for (int ks = 0; ks < 2; ks++) {
            const uint32_t koff = ks * 32 + (lane >> 4) * 16;
            uint32_t ahi[2][4], alo[2][4];
#pragma unroll
            for (int mt = 0; mt < 2; mt++) {
                uint32_t ad = sA + (uint32_t)((warp_m * 32 + mt * 16 + (lane & 15)) * ROWB) + koff;
                ldsm4(ahi[mt], ad);
                ldsm4(alo[mt], ad + MATB);
            }
#pragma unroll
            for (int half = 0; half < 2; half++) {
                uint32_t bhiR[2][4], bloR[2][4];
#pragma unroll
                for (int g2 = 0; g2 < 2; g2++) {
                    uint32_t ad = sB + (uint32_t)((warp_n * 64 + (half * 2 + g2) * 16
                                   + (lane & 15)) * ROWB) + koff;
                    ldsm4(bhiR[g2], ad);
                    ldsm4(bloR[g2], ad + MATB);
                }
#pragma unroll
                for (int mt = 0; mt < 2; mt++)
#pragma unroll
                    for (int nt = 0; nt < 4; nt++) {
                        int g2 = nt >> 1, s = nt & 1;
                        float* ac = acc[mt][half * 4 + nt];
                        mma16816(ac, ahi[mt], bhiR[g2][s], bhiR[g2][s + 2]);
                        mma16816(ac, ahi[mt], bloR[g2][s], bloR[g2][s + 2]);
                        mma16816(ac, alo[mt], bhiR[g2][s], bhiR[g2][s + 2]);
                    }
            }
        }
    };

    const int nch = K >> 5;
    load_chunk(0, 0);
    cp_commit();
    for (int c = 0; c < nch; c++) {
        if (c + 1 < nch) {
            load_chunk(c + 1, (c + 1) & 1);
            cp_commit();
            cp_wait<1>();
        } else {
            cp_wait<0>();
        }
        __syncthreads();
        compute_chunk(c & 1);
        __syncthreads();
    }

    // ---- epilogue ----
    float* sst = (float*)smem;
    if (STATS) {
        if (tid < 256) sst[tid] = 0.f;
        __syncthreads();
    }
    float colsum[16], colsq[16];
    if (STATS) {
#pragma unroll
        for (int k = 0; k < 16; k++) { colsum[k] = 0.f; colsq[k] = 0.f; }
    }
    const int r0 = lane >> 2;
    const int cq = (lane & 3) * 2;
#pragma unroll
    for (int mt = 0; mt < 2; mt++) {
#pragma unroll
        for (int nt = 0; nt < 8; nt++) {
            int col = bn0 + warp_n * 64 + nt * 8 + cq;
            float bv0 = 0.f, bv1 = 0.f;
            if (bias) { bv0 = bias[col]; bv1 = bias[col + 1]; }
#pragma unroll
            for (int h = 0; h < 2; h++) {
                int row = mrow0 + warp_m * 32 + mt * 16 + r0 + h * 8;
                float v0 = acc[mt][nt][h * 2 + 0] + bv0;
                float v1 = acc[mt][nt][h * 2 + 1] + bv1;
                if (relu) { v0 = fmaxf(v0, 0.f); v1 = fmaxf(v1, 0.f); }
                if (STATS) {
                    colsum[nt * 2] += v0;     colsq[nt * 2] = fmaf(v0, v0, colsq[nt * 2]);
                    colsum[nt * 2 + 1] += v1; colsq[nt * 2 + 1] = fmaf(v1, v1, colsq[nt * 2 + 1]);
                }
                if (ADJ) {
                    v0 = 1.f / (1.f + __expf(-v0));
                    v1 = 1.f / (1.f + __expf(-v1));
                    int rl = row - mrow0;
                    int cl = col;
                    if (rl == cl) v0 = 0.f;
                    if (rl == cl + 1) v1 = 0.f;
                    *(float2*)(Cf + (size_t)blockIdx.x * (MAXN * MAXN)
                               + (size_t)rl * MAXN + cl) = make_float2(v0, v1);
                } else {
                    size_t o = (size_t)row * Ncols + col;
                    if (Cf) *(float2*)(Cf + o) = make_float2(v0, v1);
                    if (Chi) {
                        __nv_bfloat16 h0, l0, h1, l1;
                        split_bf16(v0, h0, l0);
                        split_bf16(v1, h1, l1);
                        __nv_bfloat162 ph = {h0, h1}, pl = {l0, l1};
                        *(__nv_bfloat162*)(Chi + o) = ph;
                        *(__nv_bfloat162*)(Clo + o) = pl;
                    }
                }
            }
        }
    }
    if (STATS) {
#pragma unroll
        for (int nt = 0; nt < 8; nt++) {
            int cl = warp_n * 64 + nt * 8 + cq;
            atomicAdd(&sst[cl],           colsum[nt * 2]);
            atomicAdd(&sst[cl + 1],       colsum[nt * 2 + 1]);
            atomicAdd(&sst[128 + cl],     colsq[nt * 2]);
            atomicAdd(&sst[128 + cl + 1], colsq[nt * 2 + 1]);
        }
        __syncthreads();
        if (tid < 128) {
            atomicAdd(&g_stats[bn0 + tid], sst[tid]);
            atomicAdd(&g_stats[256 + bn0 + tid], sst[128 + tid]);
        }
    }
}

// ======== persistent fused aggregation + BN-apply (grid spin-barrier) ========
// Phase 1: per-graph aggregate -> aggout + column stats (global atomics).
// Barrier: all BB CTAs co-resident (3 CTAs/SM by smem), counter reaches `target`.
// Phase 2: v = bn(agg); v = relu(relu(v) + res); -> outZ (+ bf16 emit).
__global__ void __launch_bounds__(256)
agg_bn(const float* __restrict__ hw, const float* __restrict__ res,
       const float* __restrict__ gam, const float* __restrict__ bet,
       float* __restrict__ aggout, float* __restrict__ outZ,
       __nv_bfloat16* __restrict__ ohi, __nv_bfloat16* __restrict__ olo,
       int target)
{
    extern __shared__ float sh[];           // 128 x 128 fp32 (64KB)
    __shared__ float sstat[512];
    __shared__ float sab[512];              // a / bp per column
    int g = blockIdx.x;
    int tid = threadIdx.x;
    int lane = tid & 31;
    int w = tid >> 5;
    int nbase = g * MAXN;
    sstat[tid] = 0.f; sstat[tid + 256] = 0.f;
    for (int q = 0; q < 2; q++) {
        __syncthreads();
        int c0 = q * 128;
        for (int i = tid; i < 128 * 32; i += 256) {
            ((float4*)sh)[i] =
                *(const float4*)(hw + (size_t)(nbase + (i >> 5)) * HH + c0 + (i & 31) * 4);
        }
        __syncthreads();
        float ps0 = 0.f, ps1 = 0.f, ps2 = 0.f, ps3 = 0.f;
        float pq0 = 0.f, pq1 = 0.f, pq2 = 0.f, pq3 = 0.f;
        for (int n = w; n < MAXN; n += 8) {
            int gn = nbase + n;
            int rs = g_rowstart[gn];
            int cnt = g_deg[gn];
            float di = g_dinv[gn];
            float sl = di * di;
            float4 self = *(const float4*)&sh[n * 128 + lane * 4];
            float a0 = self.x * sl, a1 = self.y * sl, a2 = self.z * sl, a3 = self.w * sl;
            for (int e = 0; e < cnt; e++) {
                int s = __ldg(&g_csr_src[rs + e]);
                float nm = __ldg(&g_csr_norm[rs + e]);
                float4 p = *(const float4*)&sh[s * 128 + lane * 4];
                a0 = fmaf(p.x, nm, a0);
                a1 = fmaf(p.y, nm, a1);
                a2 = fmaf(p.z, nm, a2);
                a3 = fmaf(p.w, nm, a3);
            }
            *(float4*)(aggout + (size_t)gn * HH + c0 + lane * 4) = make_float4(a0, a1, a2, a3);
            ps0 += a0; ps1 += a1; ps2 += a2; ps3 += a3;
            pq0 = fmaf(a0, a0, pq0); pq1 = fmaf(a1, a1, pq1);
            pq2 = fmaf(a2, a2, pq2); pq3 = fmaf(a3, a3, pq3);
        }
        int c = c0 + lane * 4;
        atomicAdd(&sstat[c + 0], ps0); atomicAdd(&sstat[c + 1], ps1);
        atomicAdd(&sstat[c + 2], ps2); atomicAdd(&sstat[c + 3], ps3);
        atomicAdd(&sstat[256 + c + 0], pq0); atomicAdd(&sstat[256 + c + 1], pq1);
        atomicAdd(&sstat[256 + c + 2], pq2); atomicAdd(&sstat[256 + c + 3], pq3);
    }
    __syncthreads();
    atomicAdd(&g_stats[tid], sstat[tid]);
    atomicAdd(&g_stats[tid + 256], sstat[tid + 256]);

    // grid barrier (all BB CTAs resident: 66KB smem -> 3 CTAs/SM, 444 slots >= 256)
    __threadfence();
    __syncthreads();
    if (tid == 0) {
        atomicAdd(&g_bar, 1u);
        while (atomicAdd(&g_bar, 0u) < (unsigned)target) { }
    }
    __syncthreads();

    // per-column BN coefficients (stats via L1-bypassing load; atomics wrote L2)
    {
        const float invN = 1.0f / (float)NN;
        float m = __ldcv(&g_stats[tid]) * invN;
        float var = fmaxf(__ldcv(&g_stats[256 + tid]) * invN - m * m, 0.f);
        float a = gam[tid] * rsqrtf(var + 1e-5f);
        sab[tid] = a;
        sab[256 + tid] = bet[tid] - m * a;
    }
    __syncthreads();

    // phase 2: bn + relu + res + relu; own rows only (written by this CTA)
    const float4* bbase = (const float4*)(aggout + (size_t)nbase * HH);
    const float4* rbase = (const float4*)(res + (size_t)nbase * HH);
    float4* zbase = (float4*)(outZ + (size_t)nbase * HH);
    for (int i = tid; i < MAXN * HH / 4; i += 256) {
        int colq = (i & 63) * 4;
        float4 xv = bbase[i];
        float4 rv = rbase[i];
        float v0 = fmaxf(fmaxf(fmaf(xv.x, sab[colq + 0], sab[256 + colq + 0]), 0.f) + rv.x, 0.f);
        float v1 = fmaxf(fmaxf(fmaf(xv.y, sab[colq + 1], sab[256 + colq + 1]), 0.f) + rv.y, 0.f);
        float v2 = fmaxf(fmaxf(fmaf(xv.z, sab[colq + 2], sab[256 + colq + 2]), 0.f) + rv.z, 0.f);
        float v3 = fmaxf(fmaxf(fmaf(xv.w, sab[colq + 3], sab[256 + colq + 3]), 0.f) + rv.w, 0.f);
        zbase[i] = make_float4(v0, v1, v2, v3);
        if (ohi) emit4(ohi, olo, (size_t)nbase * HH + (size_t)i * 4, v0, v1, v2, v3);
    }
}

// ---------------- fused row L2 normalize + per-graph max pool ----------------
__global__ void __launch_bounds__(256)
l2norm_pool(const float* __restrict__ zin, float* __restrict__ out_z,
            __nv_bfloat16* __restrict__ ohi, __nv_bfloat16* __restrict__ olo,
            float* __restrict__ out_zg,
            __nv_bfloat16* __restrict__ shi, __nv_bfloat16* __restrict__ slo)
{
    __shared__ float rinv[MAXN];
    int g = blockIdx.x;
    int tid = threadIdx.x;
    int lane = tid & 31;
    int w = tid >> 5;
    const float* base = zin + (size_t)g * MAXN * HH;
    for (int r = w; r < MAXN; r += 8) {
        const float4* p = (const float4*)(base + (size_t)r * HH);
        float4 v0 = p[lane], v1 = p[lane + 32];
        float s = v0.x * v0.x + v0.y * v0.y + v0.z * v0.z + v0.w * v0.w
                + v1.x * v1.x + v1.y * v1.y + v1.z * v1.z + v1.w * v1.w;
#pragma unroll
        for (int o = 16; o > 0; o >>= 1) s += __shfl_xor_sync(0xffffffffu, s, o);
        if (lane == 0) rinv[r] = 1.f / fmaxf(sqrtf(s), 1e-12f);
    }
    __syncthreads();
    int c = tid;
    float mx = -1e30f;
    for (int r = 0; r < MAXN; r++) {
        float v = base[(size_t)r * HH + c] * rinv[r];
        mx = fmaxf(mx, v);
        size_t o = (size_t)(g * MAXN + r) * HH + c;
        out_z[o] = v;
        __nv_bfloat16 h, l;
        split_bf16(v, h, l);
        ohi[o] = h; olo[o] = l;
    }
    int o2 = g * HH + c;
    out_zg[o2] = mx;
    __nv_bfloat16 h, l;
    split_bf16(mx, h, l);
    shi[o2] = h; slo[o2] = l;
}

// ---------------- launcher ----------------
extern "C" void kernel_launch(void* const* d_in, const int* in_sizes, int n_in,
                              void* d_out, int out_size)
{
    const float* x   = (const float*)d_in[0];
    const int*   src = (const int*)d_in[1];
    const int*   dst = (const int*)d_in[2];
    const float* gcn_w0 = (const float*)d_in[3];
    const float* bn_g0  = (const float*)d_in[5];
    const float* bn_b0  = (const float*)d_in[6];
    const float *sc_w0, *sc_b0, *gcn_w1, *bn_g1, *bn_b1, *gcn_w2, *bn_g2, *bn_b2;
    if (in_sizes[7] == FD * HH) {  // reference-signature order
        sc_w0  = (const float*)d_in[7];
        sc_b0  = (const float*)d_in[8];
        gcn_w1 = (const float*)d_in[9];
        bn_g1  = (const float*)d_in[11];
        bn_b1  = (const float*)d_in[12];
        gcn_w2 = (const float*)d_in[13];
        bn_g2  = (const float*)d_in[15];
        bn_b2  = (const float*)d_in[16];
    } else {                        // setup_inputs dict order
        gcn_w1 = (const float*)d_in[7];
        bn_g1  = (const float*)d_in[9];
        bn_b1  = (const float*)d_in[10];
        gcn_w2 = (const float*)d_in[11];
        bn_g2  = (const float*)d_in[13];
        bn_b2  = (const float*)d_in[14];
        sc_w0  = (const float*)d_in[15];
        sc_b0  = (const float*)d_in[16];
    }
    const float* edge_w = (const float*)d_in[17];
    const float* fd_w0  = (const float*)d_in[18];
    const float* fd_b0  = (const float*)d_in[19];
    const float* fd_g0  = (const float*)d_in[20];
    const float* fd_be0 = (const float*)d_in[21];
    const float* fd_w1  = (const float*)d_in[22];
    const float* fd_b1  = (const float*)d_in[23];
    const float* fd_g1  = (const float*)d_in[24];
    const float* fd_be1 = (const float*)d_in[25];
    const float* fd_w2  = (const float*)d_in[26];
    const float* fd_b2  = (const float*)d_in[27];
    const float* ph_w0  = (const float*)d_in[28];
    const float* ph_b0  = (const float*)d_in[29];
    const float* ph_w1  = (const float*)d_in[30];
    const float* ph_b1  = (const float*)d_in[31];

    float* out = (float*)d_out;
    float* out_z   = out;
    float* out_adj = out + (size_t)NN * HH;
    float* out_xr  = out_adj + (size_t)BB * MAXN * MAXN;
    float* out_zg  = out_xr + (size_t)NN * FD;
    float* out_mlp = out_zg + (size_t)BB * HH;

    float *pA, *pB, *pZ, *pSC, *pStats, *pBfold;
    int *pDeg;
    unsigned int *pBar;
    cudaGetSymbolAddress((void**)&pA, g_bufA);
    cudaGetSymbolAddress((void**)&pB, g_bufB);
    cudaGetSymbolAddress((void**)&pZ, g_z);
    cudaGetSymbolAddress((void**)&pSC, g_sc);
    cudaGetSymbolAddress((void**)&pStats, g_stats);
    cudaGetSymbolAddress((void**)&pDeg, g_deg);
    cudaGetSymbolAddress((void**)&pBar, g_bar);
    cudaGetSymbolAddress((void**)&pBfold, g_bfold);
    __nv_bfloat16 *p0h, *p0l, *p1h, *p1l, *p2h, *p2l, *p3h, *p3l;
    __nv_bfloat16 *s0h, *s0l, *s1h, *s1l, *wh, *wl, *wfh, *wfl;
    cudaGetSymbolAddress((void**)&p0h, g_p0hi);
    cudaGetSymbolAddress((void**)&p0l, g_p0lo);
    cudaGetSymbolAddress((void**)&p1h, g_p1hi);
    cudaGetSymbolAddress((void**)&p1l, g_p1lo);
    cudaGetSymbolAddress((void**)&p2h, g_p2hi);
    cudaGetSymbolAddress((void**)&p2l, g_p2lo);
    cudaGetSymbolAddress((void**)&p3h, g_p3hi);
    cudaGetSymbolAddress((void**)&p3l, g_p3lo);
    cudaGetSymbolAddress((void**)&s0h, g_s0hi);
    cudaGetSymbolAddress((void**)&s0l, g_s0lo);
    cudaGetSymbolAddress((void**)&s1h, g_s1hi);
    cudaGetSymbolAddress((void**)&s1l, g_s1lo);
    cudaGetSymbolAddress((void**)&wh, g_whi);
    cudaGetSymbolAddress((void**)&wl, g_wlo);
    cudaGetSymbolAddress((void**)&wfh, g_wfhi);
    cudaGetSymbolAddress((void**)&wfl, g_wflo);

    const int SMEM_SZ = 2 * STAGEB;      // 81920
    const int AGG_SMEM = 128 * 128 * 4;  // 65536
    cudaFuncSetAttribute(mma_gemm<false, false>,
                         cudaFuncAttributeMaxDynamicSharedMemorySize, SMEM_SZ);
    cudaFuncSetAttribute(mma_gemm<false, true>,
                         cudaFuncAttributeMaxDynamicSharedMemorySize, SMEM_SZ);
    cudaFuncSetAttribute(mma_gemm<true, false>,
                         cudaFuncAttributeMaxDynamicSharedMemorySize, SMEM_SZ);
    cudaFuncSetAttribute(agg_bn,
                         cudaFuncAttributeMaxDynamicSharedMemorySize, AGG_SMEM);

    // ---- static side streams + events (created once, on the uncaptured call) ----
    static cudaStream_t sA = nullptr, sBst = nullptr;
    static cudaEvent_t ev[8];
    if (!sA) {
        cudaStreamCreateWithFlags(&sA, cudaStreamNonBlocking);
        cudaStreamCreateWithFlags(&sBst, cudaStreamNonBlocking);
        for (int i = 0; i < 8; i++)
            cudaEventCreateWithFlags(&ev[i], cudaEventDisableTiming);
    }

    dim3 gBig(NN / 128, HH / 128);   // (256, 2)
    dim3 gXr(NN / 128, FD / 128);    // (256, 1)
    dim3 gAdj(NN / 128, 1);          // (256, 1)
    dim3 gPh(BB / 128, HH / 128);    // (2, 2)

    // ================= phase 1: convs (main) || CSR precompute (sA) ==========
    cudaEventRecord(ev[0], 0);
    cudaStreamWaitEvent(sA, ev[0], 0);
    cudaMemsetAsync(pDeg, 0, NN * sizeof(int), sA);
    k_count_deg<<<EE / 256, 256, 0, sA>>>(dst);
    k_scan_rows<<<BB, 128, 0, sA>>>();
    k_fill_csr<<<EE / 256, 256, 0, sA>>>(src, dst);
    cudaEventRecord(ev[1], sA);               // CSR ready

    cudaMemsetAsync(pBar, 0, sizeof(unsigned int), 0);   // barrier counter reset
    a_conv<<<NN * FD / 1024, 256>>>(x, p0h, p0l, NN * FD / 4);
    WList wlist;
    wlist.w[0] = gcn_w0; wlist.kd[0] = FD; wlist.nd[0] = HH;
    wlist.w[1] = sc_w0;  wlist.kd[1] = FD; wlist.nd[1] = HH;
    wlist.w[2] = gcn_w1; wlist.kd[2] = HH; wlist.nd[2] = HH;
    wlist.w[3] = gcn_w2; wlist.kd[3] = HH; wlist.nd[3] = HH;
    wlist.w[4] = edge_w; wlist.kd[4] = HH; wlist.nd[4] = HH;
    wlist.w[5] = fd_w0;  wlist.kd[5] = HH; wlist.nd[5] = HH;
    wlist.w[6] = fd_w1;  wlist.kd[6] = HH; wlist.nd[6] = HH;
    wlist.w[7] = fd_w2;  wlist.kd[7] = HH; wlist.nd[7] = FD;
    wlist.w[8] = ph_w0;  wlist.kd[8] = HH; wlist.nd[8] = HH;
    wlist.w[9] = ph_w1;  wlist.kd[9] = HH; wlist.nd[9] = HH;
    w_conv_all<<<dim3(256, 10), 256>>>(wlist, wh, wl);
    cudaEventRecord(ev[2], 0);                // convs ready

    // sc0 GEMM on sBst, concurrent with gcn0 GEMM on main
    cudaStreamWaitEvent(sBst, ev[2], 0);
    mma_gemm<false, false><<<gBig, 256, SMEM_SZ, sBst>>>(p0h, p0l, wh + 1 * 65536, wl + 1 * 65536,
                                                         sc_b0, pSC, nullptr, nullptr, FD, HH, 0);
    cudaEventRecord(ev[3], sBst);             // shortcut ready

    // ---- block 0 ----
    mma_gemm<false, false><<<gBig, 256, SMEM_SZ>>>(p0h, p0l, wh + 0 * 65536, wl + 0 * 65536,
                                                   nullptr, pA, nullptr, nullptr, FD, HH, 0);
    cudaMemsetAsync(pStats, 0, 2 * HH * sizeof(float), 0);
    cudaStreamWaitEvent(0, ev[1], 0);         // need CSR
    cudaStreamWaitEvent(0, ev[3], 0);         // need shortcut (phase 2 residual)
    agg_bn<<<BB, 256, AGG_SMEM>>>(pA, pSC, bn_g0, bn_b0, pB, pZ, p0h, p0l, 1 * BB);

    // ---- block 1 ----
    mma_gemm<false, false><<<gBig, 256, SMEM_SZ>>>(p0h, p0l, wh + 2 * 65536, wl + 2 * 65536,
                                                   nullptr, pA, nullptr, nullptr, HH, HH, 0);
    cudaMemsetAsync(pStats, 0, 2 * HH * sizeof(float), 0);
    agg_bn<<<BB, 256, AGG_SMEM>>>(pA, pZ, bn_g1, bn_b1, pB, pZ, p0h, p0l, 2 * BB);

    // ---- block 2 ----
    mma_gemm<false, false><<<gBig, 256, SMEM_SZ>>>(p0h, p0l, wh + 3 * 65536, wl + 3 * 65536,
                                                   nullptr, pA, nullptr, nullptr, HH, HH, 0);
    cudaMemsetAsync(pStats, 0, 2 * HH * sizeof(float), 0);
    agg_bn<<<BB, 256, AGG_SMEM>>>(pA, pZ, bn_g2, bn_b2, pB, pZ, nullptr, nullptr, 3 * BB);

    // ---- fused l2 normalize (output 0) + max pool (output 3) ----
    l2norm_pool<<<BB, 256>>>(pZ, out_z, p0h, p0l, out_zg, s0h, s0l);
    cudaEventRecord(ev[4], 0);                // z (fp32 + bf16) + z_g ready

    // ================= phase 2: three independent decoder chains =============
    // sA: edge decoder -> out_adj
    cudaStreamWaitEvent(sA, ev[4], 0);
    mma_gemm<false, false><<<gBig, 256, SMEM_SZ, sA>>>(p0h, p0l, wh + 4 * 65536, wl + 4 * 65536,
                                                       nullptr, nullptr, p1h, p1l, HH, HH, 0);
    mma_gemm<true, false><<<gAdj, 256, SMEM_SZ, sA>>>(p1h, p1l, p0h, p0l,
                                                      nullptr, out_adj, nullptr, nullptr, HH, MAXN, 0);
    cudaEventRecord(ev[5], sA);

    // sBst: pooling head -> out_mlp
    cudaStreamWaitEvent(sBst, ev[4], 0);
    mma_gemm<false, false><<<gPh, 256, SMEM_SZ, sBst>>>(s0h, s0l, wh + 8 * 65536, wl + 8 * 65536,
                                                        ph_b0, nullptr, s1h, s1l, HH, HH, 1);
    mma_gemm<false, false><<<gPh, 256, SMEM_SZ, sBst>>>(s1h, s1l, wh + 9 * 65536, wl + 9 * 65536,
                                                        ph_b1, out_mlp, nullptr, nullptr, HH, HH, 0);
    cudaEventRecord(ev[6], sBst);

    // main: feature decoder with BN folded into weights
    // h1 = relu(z@fd_w0 + b0): STATS over h1, bf16 emit only (no fp32 write)
    cudaMemsetAsync(pStats, 0, 2 * HH * sizeof(float), 0);
    mma_gemm<false, true><<<gBig, 256, SMEM_SZ>>>(p0h, p0l, wh + 5 * 65536, wl + 5 * 65536,
                                                  fd_b0, nullptr, p2h, p2l, HH, HH, 1);
    // fold bn0 into fd_w1: W' = diag(a) fd_w1, b' = fd_b1 + bp^T fd_w1
    fold_bn_w<<<HH, 256>>>(fd_w1, fd_b1, fd_g0, fd_be0, wfh, wfl, pBfold, HH);
    cudaMemsetAsync(pStats, 0, 2 * HH * sizeof(float), 0);
    // h2 = relu(h1@W' + b'): STATS over h2, bf16 emit -> p3
    mma_gemm<false, true><<<gBig, 256, SMEM_SZ>>>(p2h, p2l, wfh, wfl,
                                                  pBfold, nullptr, p3h, p3l, HH, HH, 1);
    // fold bn1 into fd_w2
    fold_bn_w<<<FD, 256>>>(fd_w2, fd_b2, fd_g1, fd_be1, wfh, wfl, pBfold, FD);
    // x_recon = h2@W'' + b''
    mma_gemm<false, false><<<gXr, 256, SMEM_SZ>>>(p3h, p3l, wfh, wfl,
                                                  pBfold, out_xr, nullptr, nullptr, HH, FD, 0);

    // join side streams back into the capture-origin stream
    cudaStreamWaitEvent(0, ev[5], 0);
    cudaStreamWaitEvent(0, ev[6], 0);
}

// round 12
// speedup vs baseline: 1.2284x; 1.0702x over previous
#include <cuda_runtime.h>
#include <cuda_bf16.h>
#include <math.h>
#include <stdint.h>

// Problem constants
#define NN   32768      // nodes
#define HH   256        // hidden
#define FD   128        // input feature dim
#define BB   256        // graphs
#define MAXN 128        // nodes per graph
#define EE   524288     // edges
#define EPG  2048       // edges per graph (EE/BB)

// ======================= PTX helpers (baseline compute_100 only) =======================
__device__ __forceinline__ uint32_t smem_to_u32(const void* smem_ptr) {
    uint32_t addr;
    asm("{ .reg .u64 tmp; cvta.to.shared.u64 tmp, %1; cvt.u32.u64 %0, tmp; }"
        : "=r"(addr) : "l"(smem_ptr));
    return addr;
}
__device__ __forceinline__ void ldsm4(uint32_t* r, uint32_t addr) {
    asm volatile("ldmatrix.sync.aligned.m8n8.x4.shared.b16 {%0,%1,%2,%3}, [%4];"
        : "=r"(r[0]), "=r"(r[1]), "=r"(r[2]), "=r"(r[3]) : "r"(addr));
}
__device__ __forceinline__ void mma16816(float* d, const uint32_t* a, uint32_t b0, uint32_t b1) {
    asm volatile(
        "mma.sync.aligned.m16n8k16.row.col.f32.bf16.bf16.f32 "
        "{%0,%1,%2,%3}, {%4,%5,%6,%7}, {%8,%9}, {%0,%1,%2,%3};"
        : "+f"(d[0]), "+f"(d[1]), "+f"(d[2]), "+f"(d[3])
        : "r"(a[0]), "r"(a[1]), "r"(a[2]), "r"(a[3]), "r"(b0), "r"(b1));
}
__device__ __forceinline__ void cp16(uint32_t s, const void* g) {
    asm volatile("cp.async.cg.shared.global [%0], [%1], 16;" :: "r"(s), "l"(g) : "memory");
}
__device__ __forceinline__ void cp_commit() {
    asm volatile("cp.async.commit_group;" ::: "memory");
}
template<int NG> __device__ __forceinline__ void cp_wait() {
    asm volatile("cp.async.wait_group %0;" :: "n"(NG) : "memory");
}

// ---------------- scratch (device globals) ----------------
__device__ __align__(256) float g_bufB[(size_t)NN * HH];
__device__ __align__(256) float g_z[(size_t)NN * HH];
__device__ __align__(256) float g_sc[(size_t)NN * HH];
__device__ float g_dinv[NN];
__device__ int   g_deg[NN];
__device__ int   g_rowstart[NN];
__device__ int   g_cursor[NN];
__device__ int   g_csr_src[EE];
__device__ float g_csr_norm[EE];
__device__ float g_stats[2 * HH];
__device__ float g_bfold[HH];

// bf16 hi/lo operand buffers
__device__ __align__(256) __nv_bfloat16 g_p0hi[(size_t)NN * HH];
__device__ __align__(256) __nv_bfloat16 g_p0lo[(size_t)NN * HH];
__device__ __align__(256) __nv_bfloat16 g_p1hi[(size_t)NN * HH];
__device__ __align__(256) __nv_bfloat16 g_p1lo[(size_t)NN * HH];
__device__ __align__(256) __nv_bfloat16 g_p2hi[(size_t)NN * HH];
__device__ __align__(256) __nv_bfloat16 g_p2lo[(size_t)NN * HH];
__device__ __align__(256) __nv_bfloat16 g_p3hi[(size_t)NN * HH];
__device__ __align__(256) __nv_bfloat16 g_p3lo[(size_t)NN * HH];
__device__ __align__(256) __nv_bfloat16 g_s0hi[BB * HH];
__device__ __align__(256) __nv_bfloat16 g_s0lo[BB * HH];
__device__ __align__(256) __nv_bfloat16 g_s1hi[BB * HH];
__device__ __align__(256) __nv_bfloat16 g_s1lo[BB * HH];
__device__ __align__(256) __nv_bfloat16 g_whi[10 * 65536];  // 10 transposed weights
__device__ __align__(256) __nv_bfloat16 g_wlo[10 * 65536];
__device__ __align__(256) __nv_bfloat16 g_wfhi[65536];      // folded weight scratch
__device__ __align__(256) __nv_bfloat16 g_wflo[65536];

// ---------------- precompute: degrees, dinv, CSR ----------------
__global__ void k_count_deg(const int* __restrict__ dst) {
    int e = blockIdx.x * 256 + threadIdx.x;
    if (e >= EE) return;
    int g = e >> 11;
    atomicAdd(&g_deg[g * MAXN + dst[e]], 1);
}
__global__ void k_scan_rows() {
    int g = blockIdx.x;
    int t = threadIdx.x;
    int n = g * MAXN + t;
    __shared__ int s[MAXN];
    int d = g_deg[n];
    g_dinv[n] = rsqrtf((float)(d + 1));   // self loop adds 1
    s[t] = d;
    __syncthreads();
    for (int off = 1; off < MAXN; off <<= 1) {
        int v = (t >= off) ? s[t - off] : 0;
        __syncthreads();
        s[t] += v;
        __syncthreads();
    }
    int start = g * EPG + s[t] - d;
    g_rowstart[n] = start;
    g_cursor[n] = start;
}
__global__ void k_fill_csr(const int* __restrict__ src, const int* __restrict__ dst) {
    int e = blockIdx.x * 256 + threadIdx.x;
    if (e >= EE) return;
    int g = e >> 11;
    int s = src[e], d = dst[e];
    int slot = atomicAdd(&g_cursor[g * MAXN + d], 1);
    g_csr_src[slot] = s;
    g_csr_norm[slot] = g_dinv[g * MAXN + s] * g_dinv[g * MAXN + d];
}

// ---------------- fp32 -> bf16 hi/lo converts ----------------
__device__ __forceinline__ void split_bf16(float v, __nv_bfloat16& h, __nv_bfloat16& l) {
    h = __float2bfloat16(v);
    l = __float2bfloat16(v - __bfloat162float(h));
}
__device__ __forceinline__ void emit4(__nv_bfloat16* hi, __nv_bfloat16* lo, size_t o,
                                      float a, float b, float c, float d) {
    __nv_bfloat16 h0, l0, h1, l1, h2, l2, h3, l3;
    split_bf16(a, h0, l0); split_bf16(b, h1, l1);
    split_bf16(c, h2, l2); split_bf16(d, h3, l3);
    __nv_bfloat162 hv0 = {h0, h1}, hv1 = {h2, h3};
    __nv_bfloat162 lv0 = {l0, l1}, lv1 = {l2, l3};
    *(__nv_bfloat162*)(hi + o) = hv0;
    *(__nv_bfloat162*)(hi + o + 2) = hv1;
    *(__nv_bfloat162*)(lo + o) = lv0;
    *(__nv_bfloat162*)(lo + o + 2) = lv1;
}
__global__ void a_conv(const float* __restrict__ A, __nv_bfloat16* __restrict__ hi,
                       __nv_bfloat16* __restrict__ lo, int n4) {
    int i = blockIdx.x * 256 + threadIdx.x;
    if (i >= n4) return;
    float4 v = ((const float4*)A)[i];
    emit4(hi, lo, (size_t)i * 4, v.x, v.y, v.z, v.w);
}
struct WList { const float* w[10]; int kd[10]; int nd[10]; };
__global__ void w_conv_all(WList wl, __nv_bfloat16* __restrict__ hi,
                           __nv_bfloat16* __restrict__ lo) {
    int widx = blockIdx.y;
    int i = blockIdx.x * 256 + threadIdx.x;
    int Kd = wl.kd[widx], Nd = wl.nd[widx];
    if (i >= Kd * Nd) return;
    int k = i / Nd, n = i - k * Nd;
    __nv_bfloat16 h, l;
    split_bf16(wl.w[widx][i], h, l);
    hi[(size_t)widx * 65536 + (size_t)n * Kd + k] = h;
    lo[(size_t)widx * 65536 + (size_t)n * Kd + k] = l;
}

// ---- fold BN affine into next GEMM weights ----
__global__ void fold_bn_w(const float* __restrict__ W, const float* __restrict__ bias_in,
                          const float* __restrict__ gam, const float* __restrict__ bet,
                          __nv_bfloat16* __restrict__ whi, __nv_bfloat16* __restrict__ wlo,
                          float* __restrict__ bias_out, int Nd)
{
    __shared__ float red[256];
    int k = blockIdx.x;
    int j = threadIdx.x;
    const float invN = 1.0f / (float)NN;
    float m = g_stats[j] * invN;
    float var = fmaxf(g_stats[256 + j] * invN - m * m, 0.f);
    float a = gam[j] * rsqrtf(var + 1e-5f);
    float bp = bet[j] - m * a;
    float w = W[j * Nd + k];
    __nv_bfloat16 h, l;
    split_bf16(a * w, h, l);
    whi[(size_t)k * 256 + j] = h;
    wlo[(size_t)k * 256 + j] = l;
    red[j] = bp * w;
    __syncthreads();
    for (int o = 128; o > 0; o >>= 1) {
        if (j < o) red[j] += red[j + o];
        __syncthreads();
    }
    if (j == 0) bias_out[k] = bias_in[k] + red[0];
}

// ======================= mma.sync split-x3 GEMM =======================
// AGG: epilogue spills the 128x128 tile to smem and performs per-graph CSR
// aggregation + BN stats locally (blockIdx.x == graph id, blockIdx.y == col half).
#define ROWB   80
#define MATB   10240            // 128 rows * 80B
#define STAGEB 40960            // 4 matrices (Ahi,Alo,Bhi,Blo)
#define TSTRIDE 132             // padded tile row stride (floats)
template<bool ADJ, bool STATS, bool AGG>
__global__ void __launch_bounds__(256, 2)
mma_gemm(const __nv_bfloat16* __restrict__ Ahi, const __nv_bfloat16* __restrict__ Alo,
         const __nv_bfloat16* __restrict__ Bhi, const __nv_bfloat16* __restrict__ Blo,
         const float* __restrict__ bias, float* __restrict__ Cf,
         __nv_bfloat16* __restrict__ Chi, __nv_bfloat16* __restrict__ Clo,
         int K, int Ncols, int relu)
{
    extern __shared__ char smem[];
    const uint32_t sb = smem_to_u32(smem);
    const int tid = threadIdx.x;
    const int lane = tid & 31;
    const int wid = tid >> 5;
    const int warp_m = wid & 3;
    const int warp_n = wid >> 2;
    const int mrow0 = blockIdx.x * 128;
    const int bn0 = blockIdx.y * 128;
    const int brow0 = ADJ ? mrow0 : bn0;

    const __nv_bfloat16* baseA_hi = Ahi + (size_t)mrow0 * K;
    const __nv_bfloat16* baseA_lo = Alo + (size_t)mrow0 * K;
    const __nv_bfloat16* baseB_hi = Bhi + (size_t)brow0 * K;
    const __nv_bfloat16* baseB_lo = Blo + (size_t)brow0 * K;

    float acc[2][8][4];
#pragma unroll
    for (int mt = 0; mt < 2; mt++)
#pragma unroll
        for (int nt = 0; nt < 8; nt++)
#pragma unroll
            for (int v = 0; v < 4; v++) acc[mt][nt][v] = 0.f;

    auto load_chunk = [&](int c, int stage) {
        const int kc = c << 5;
        const uint32_t sbase = sb + stage * STAGEB;
#pragma unroll
        for (int t = 0; t < 8; t++) {
            int i = t * 256 + tid;
            int mat = i >> 9;
            int r = (i >> 2) & 127;
            int q = i & 3;
            const __nv_bfloat16* g;
            if      (mat == 0) g = baseA_hi + (size_t)r * K + kc + q * 8;
            else if (mat == 1) g = baseA_lo + (size_t)r * K + kc + q * 8;
            else if (mat == 2) g = baseB_hi + (size_t)r * K + kc + q * 8;
            else               g = baseB_lo + (size_t)r * K + kc + q * 8;
            cp16(sbase + mat * MATB + r * ROWB + q * 16, g);
        }
    };

    auto compute_chunk = [&](int stage) {
        const uint32_t sA = sb + stage * STAGEB;
        const uint32_t sB = sA + 2 * MATB;
#pragma unroll
        for (int ks = 0; ks < 2; ks++) {
            const uint32_t koff = ks * 32 + (lane >> 4) * 16;
            uint32_t ahi[2][4], alo[2][4];
#pragma unroll
            for (int mt = 0; mt < 2; mt++) {
                uint32_t ad = sA + (uint32_t)((warp_m * 32 + mt * 16 + (lane & 15)) * ROWB) + koff;
                ldsm4(ahi[mt], ad);
                ldsm4(alo[mt], ad + MATB);
            }
#pragma unroll
            for (int half = 0; half < 2; half++) {
                uint32_t bhiR[2][4], bloR[2][4];
#pragma unroll
                for (int g2 = 0; g2 < 2; g2++) {
                    uint32_t ad = sB + (uint32_t)((warp_n * 64 + (half * 2 + g2) * 16
                                   + (lane & 15)) * ROWB) + koff;
                    ldsm4(bhiR[g2], ad);
                    ldsm4(bloR[g2], ad + MATB);
                }
#pragma unroll
                for (int mt = 0; mt < 2; mt++)
#pragma unroll
                    for (int nt = 0; nt < 4; nt++) {
                        int g2 = nt >> 1, s = nt & 1;
                        float* ac = acc[mt][half * 4 + nt];
                        mma16816(ac, ahi[mt], bhiR[g2][s], bhiR[g2][s + 2]);
                        mma16816(ac, ahi[mt], bloR[g2][s], bloR[g2][s + 2]);
                        mma16816(ac, alo[mt], bhiR[g2][s], bhiR[g2][s + 2]);
                    }
            }
        }
    };

    const int nch = K >> 5;
    load_chunk(0, 0);
    cp_commit();
    for (int c = 0; c < nch; c++) {
        if (c + 1 < nch) {
            load_chunk(c + 1, (c + 1) & 1);
            cp_commit();
            cp_wait<1>();
        } else {
            cp_wait<0>();
        }
        __syncthreads();
        compute_chunk(c & 1);
        __syncthreads();
    }

    // ---- epilogue ----
    float* tile = (float*)smem;                    // AGG: 128 x TSTRIDE tile
    float* astat = tile + 128 * TSTRIDE;           // AGG: 256 floats (sum|sq)
    float* sst = (float*)smem;                     // STATS: 256 floats
    if (STATS || AGG) {
        if (tid < 256) (AGG ? astat : sst)[tid] = 0.f;
        if (STATS) __syncthreads();
    }
    float colsum[16], colsq[16];
    if (STATS) {
#pragma unroll
        for (int k = 0; k < 16; k++) { colsum[k] = 0.f; colsq[k] = 0.f; }
    }
    const int r0 = lane >> 2;
    const int cq = (lane & 3) * 2;
#pragma unroll
    for (int mt = 0; mt < 2; mt++) {
#pragma unroll
        for (int nt = 0; nt < 8; nt++) {
            int col = bn0 + warp_n * 64 + nt * 8 + cq;
            float bv0 = 0.f, bv1 = 0.f;
            if (bias) { bv0 = bias[col]; bv1 = bias[col + 1]; }
#pragma unroll
            for (int h = 0; h < 2; h++) {
                int row = mrow0 + warp_m * 32 + mt * 16 + r0 + h * 8;
                float v0 = acc[mt][nt][h * 2 + 0] + bv0;
                float v1 = acc[mt][nt][h * 2 + 1] + bv1;
                if (relu) { v0 = fmaxf(v0, 0.f); v1 = fmaxf(v1, 0.f); }
                if (STATS) {
                    colsum[nt * 2] += v0;     colsq[nt * 2] = fmaf(v0, v0, colsq[nt * 2]);
                    colsum[nt * 2 + 1] += v1; colsq[nt * 2 + 1] = fmaf(v1, v1, colsq[nt * 2 + 1]);
                }
                if (AGG) {
                    int rl = row - mrow0;
                    int cl = col - bn0;
                    *(float2*)&tile[rl * TSTRIDE + cl] = make_float2(v0, v1);
                } else if (ADJ) {
                    v0 = 1.f / (1.f + __expf(-v0));
                    v1 = 1.f / (1.f + __expf(-v1));
                    int rl = row - mrow0;
                    int cl = col;
                    if (rl == cl) v0 = 0.f;
                    if (rl == cl + 1) v1 = 0.f;
                    *(float2*)(Cf + (size_t)blockIdx.x * (MAXN * MAXN)
                               + (size_t)rl * MAXN + cl) = make_float2(v0, v1);
                } else {
                    size_t o = (size_t)row * Ncols + col;
                    if (Cf) *(float2*)(Cf + o) = make_float2(v0, v1);
                    if (Chi) {
                        __nv_bfloat16 h0, l0, h1, l1;
                        split_bf16(v0, h0, l0);
                        split_bf16(v1, h1, l1);
                        __nv_bfloat162 ph = {h0, h1}, pl = {l0, l1};
                        *(__nv_bfloat162*)(Chi + o) = ph;
                        *(__nv_bfloat162*)(Clo + o) = pl;
                    }
                }
            }
        }
    }
    if (AGG) {
        __syncthreads();
        // per-graph aggregation from the smem tile (rows = nodes of graph blockIdx.x)
        float ps0 = 0.f, ps1 = 0.f, ps2 = 0.f, ps3 = 0.f;
        float pq0 = 0.f, pq1 = 0.f, pq2 = 0.f, pq3 = 0.f;
        for (int n = wid; n < MAXN; n += 8) {
            int gn = mrow0 + n;
            int rs = g_rowstart[gn];
            int cnt = g_deg[gn];
            float di = g_dinv[gn];
            float sl = di * di;
            float4 self = *(const float4*)&tile[n * TSTRIDE + lane * 4];
            float a0 = self.x * sl, a1 = self.y * sl, a2 = self.z * sl, a3 = self.w * sl;
            for (int e = 0; e < cnt; e++) {
                int s = __ldg(&g_csr_src[rs + e]);
                float nm = __ldg(&g_csr_norm[rs + e]);
                float4 p = *(const float4*)&tile[s * TSTRIDE + lane * 4];
                a0 = fmaf(p.x, nm, a0);
                a1 = fmaf(p.y, nm, a1);
                a2 = fmaf(p.z, nm, a2);
                a3 = fmaf(p.w, nm, a3);
            }
            *(float4*)(Cf + (size_t)gn * HH + bn0 + lane * 4) = make_float4(a0, a1, a2, a3);
            ps0 += a0; ps1 += a1; ps2 += a2; ps3 += a3;
            pq0 = fmaf(a0, a0, pq0); pq1 = fmaf(a1, a1, pq1);
            pq2 = fmaf(a2, a2, pq2); pq3 = fmaf(a3, a3, pq3);
        }
        int c = lane * 4;
        atomicAdd(&astat[c + 0], ps0); atomicAdd(&astat[c + 1], ps1);
        atomicAdd(&astat[c + 2], ps2); atomicAdd(&astat[c + 3], ps3);
        atomicAdd(&astat[128 + c + 0], pq0); atomicAdd(&astat[128 + c + 1], pq1);
        atomicAdd(&astat[128 + c + 2], pq2); atomicAdd(&astat[128 + c + 3], pq3);
        __syncthreads();
        if (tid < 128) {
            atomicAdd(&g_stats[bn0 + tid], astat[tid]);
            atomicAdd(&g_stats[256 + bn0 + tid], astat[128 + tid]);
        }
    }
    if (STATS) {
#pragma unroll
        for (int nt = 0; nt < 8; nt++) {
            int cl = warp_n * 64 + nt * 8 + cq;
            atomicAdd(&sst[cl],           colsum[nt * 2]);
            atomicAdd(&sst[cl + 1],       colsum[nt * 2 + 1]);
            atomicAdd(&sst[128 + cl],     colsq[nt * 2]);
            atomicAdd(&sst[128 + cl + 1], colsq[nt * 2 + 1]);
        }
        __syncthreads();
        if (tid < 128) {
            atomicAdd(&g_stats[bn0 + tid], sst[tid]);
            atomicAdd(&g_stats[256 + bn0 + tid], sst[128 + tid]);
        }
    }
}

// ---------------- BatchNorm apply (vectorized, + bf16 emit) ----------------
// mode 0: out = bn(x); mode 1: out = relu(relu(bn(x)) + res). float4 per thread.
__global__ void bn_apply(const float* __restrict__ xin, const float* __restrict__ res,
                         const float* __restrict__ gam, const float* __restrict__ bet,
                         float* __restrict__ outp,
                         __nv_bfloat16* __restrict__ ohi, __nv_bfloat16* __restrict__ olo,
                         int mode)
{
    size_t i4 = ((size_t)blockIdx.x * 256 + threadIdx.x) * 4;
    int col = (int)(i4 & 255);
    const float invN = 1.0f / (float)NN;
    float a[4], bp[4];
#pragma unroll
    for (int k = 0; k < 4; k++) {
        float m = g_stats[col + k] * invN;
        float var = fmaxf(g_stats[HH + col + k] * invN - m * m, 0.f);
        float aa = gam[col + k] * rsqrtf(var + 1e-5f);
        a[k] = aa;
        bp[k] = bet[col + k] - m * aa;
    }
    float4 xv = *(const float4*)(xin + i4);
    float v[4] = { fmaf(xv.x, a[0], bp[0]), fmaf(xv.y, a[1], bp[1]),
                   fmaf(xv.z, a[2], bp[2]), fmaf(xv.w, a[3], bp[3]) };
    if (mode == 1) {
        float4 rv = *(const float4*)(res + i4);
        v[0] = fmaxf(fmaxf(v[0], 0.f) + rv.x, 0.f);
        v[1] = fmaxf(fmaxf(v[1], 0.f) + rv.y, 0.f);
        v[2] = fmaxf(fmaxf(v[2], 0.f) + rv.z, 0.f);
        v[3] = fmaxf(fmaxf(v[3], 0.f) + rv.w, 0.f);
    }
    if (outp) *(float4*)(outp + i4) = make_float4(v[0], v[1], v[2], v[3]);
    if (ohi) emit4(ohi, olo, i4, v[0], v[1], v[2], v[3]);
}

// ---------------- fused row L2 normalize + per-graph max pool ----------------
__global__ void __launch_bounds__(256)
l2norm_pool(const float* __restrict__ zin, float* __restrict__ out_z,
            __nv_bfloat16* __restrict__ ohi, __nv_bfloat16* __restrict__ olo,
            float* __restrict__ out_zg,
            __nv_bfloat16* __restrict__ shi, __nv_bfloat16* __restrict__ slo)
{
    __shared__ float rinv[MAXN];
    int g = blockIdx.x;
    int tid = threadIdx.x;
    int lane = tid & 31;
    int w = tid >> 5;
    const float* base = zin + (size_t)g * MAXN * HH;
    for (int r = w; r < MAXN; r += 8) {
        const float4* p = (const float4*)(base + (size_t)r * HH);
        float4 v0 = p[lane], v1 = p[lane + 32];
        float s = v0.x * v0.x + v0.y * v0.y + v0.z * v0.z + v0.w * v0.w
                + v1.x * v1.x + v1.y * v1.y + v1.z * v1.z + v1.w * v1.w;
#pragma unroll
        for (int o = 16; o > 0; o >>= 1) s += __shfl_xor_sync(0xffffffffu, s, o);
        if (lane == 0) rinv[r] = 1.f / fmaxf(sqrtf(s), 1e-12f);
    }
    __syncthreads();
    int c = tid;
    float mx = -1e30f;
    for (int r = 0; r < MAXN; r++) {
        float v = base[(size_t)r * HH + c] * rinv[r];
        mx = fmaxf(mx, v);
        size_t o = (size_t)(g * MAXN + r) * HH + c;
        out_z[o] = v;
        __nv_bfloat16 h, l;
        split_bf16(v, h, l);
        ohi[o] = h; olo[o] = l;
    }
    int o2 = g * HH + c;
    out_zg[o2] = mx;
    __nv_bfloat16 h, l;
    split_bf16(mx, h, l);
    shi[o2] = h; slo[o2] = l;
}

// ---------------- launcher ----------------
extern "C" void kernel_launch(void* const* d_in, const int* in_sizes, int n_in,
                              void* d_out, int out_size)
{
    const float* x   = (const float*)d_in[0];
    const int*   src = (const int*)d_in[1];
    const int*   dst = (const int*)d_in[2];
    const float* gcn_w0 = (const float*)d_in[3];
    const float* bn_g0  = (const float*)d_in[5];
    const float* bn_b0  = (const float*)d_in[6];
    const float *sc_w0, *sc_b0, *gcn_w1, *bn_g1, *bn_b1, *gcn_w2, *bn_g2, *bn_b2;
    if (in_sizes[7] == FD * HH) {  // reference-signature order
        sc_w0  = (const float*)d_in[7];
        sc_b0  = (const float*)d_in[8];
        gcn_w1 = (const float*)d_in[9];
        bn_g1  = (const float*)d_in[11];
        bn_b1  = (const float*)d_in[12];
        gcn_w2 = (const float*)d_in[13];
        bn_g2  = (const float*)d_in[15];
        bn_b2  = (const float*)d_in[16];
    } else {                        // setup_inputs dict order
        gcn_w1 = (const float*)d_in[7];
        bn_g1  = (const float*)d_in[9];
        bn_b1  = (const float*)d_in[10];
        gcn_w2 = (const float*)d_in[11];
        bn_g2  = (const float*)d_in[13];
        bn_b2  = (const float*)d_in[14];
        sc_w0  = (const float*)d_in[15];
        sc_b0  = (const float*)d_in[16];
    }
    const float* edge_w = (const float*)d_in[17];
    const float* fd_w0  = (const float*)d_in[18];
    const float* fd_b0  = (const float*)d_in[19];
    const float* fd_g0  = (const float*)d_in[20];
    const float* fd_be0 = (const float*)d_in[21];
    const float* fd_w1  = (const float*)d_in[22];
    const float* fd_b1  = (const float*)d_in[23];
    const float* fd_g1  = (const float*)d_in[24];
    const float* fd_be1 = (const float*)d_in[25];
    const float* fd_w2  = (const float*)d_in[26];
    const float* fd_b2  = (const float*)d_in[27];
    const float* ph_w0  = (const float*)d_in[28];
    const float* ph_b0  = (const float*)d_in[29];
    const float* ph_w1  = (const float*)d_in[30];
    const float* ph_b1  = (const float*)d_in[31];

    float* out = (float*)d_out;
    float* out_z   = out;
    float* out_adj = out + (size_t)NN * HH;
    float* out_xr  = out_adj + (size_t)BB * MAXN * MAXN;
    float* out_zg  = out_xr + (size_t)NN * FD;
    float* out_mlp = out_zg + (size_t)BB * HH;

    float *pB, *pZ, *pSC, *pStats, *pBfold;
    int *pDeg;
    cudaGetSymbolAddress((void**)&pB, g_bufB);
    cudaGetSymbolAddress((void**)&pZ, g_z);
    cudaGetSymbolAddress((void**)&pSC, g_sc);
    cudaGetSymbolAddress((void**)&pStats, g_stats);
    cudaGetSymbolAddress((void**)&pDeg, g_deg);
    cudaGetSymbolAddress((void**)&pBfold, g_bfold);
    __nv_bfloat16 *p0h, *p0l, *p1h, *p1l, *p2h, *p2l, *p3h, *p3l;
    __nv_bfloat16 *s0h, *s0l, *s1h, *s1l, *wh, *wl, *wfh, *wfl;
    cudaGetSymbolAddress((void**)&p0h, g_p0hi);
    cudaGetSymbolAddress((void**)&p0l, g_p0lo);
    cudaGetSymbolAddress((void**)&p1h, g_p1hi);
    cudaGetSymbolAddress((void**)&p1l, g_p1lo);
    cudaGetSymbolAddress((void**)&p2h, g_p2hi);
    cudaGetSymbolAddress((void**)&p2l, g_p2lo);
    cudaGetSymbolAddress((void**)&p3h, g_p3hi);
    cudaGetSymbolAddress((void**)&p3l, g_p3lo);
    cudaGetSymbolAddress((void**)&s0h, g_s0hi);
    cudaGetSymbolAddress((void**)&s0l, g_s0lo);
    cudaGetSymbolAddress((void**)&s1h, g_s1hi);
    cudaGetSymbolAddress((void**)&s1l, g_s1lo);
    cudaGetSymbolAddress((void**)&wh, g_whi);
    cudaGetSymbolAddress((void**)&wl, g_wlo);
    cudaGetSymbolAddress((void**)&wfh, g_wfhi);
    cudaGetSymbolAddress((void**)&wfl, g_wflo);

    const int SMEM_SZ = 2 * STAGEB;      // 81920 (>= AGG tile 128*132*4 + 1KB)
    cudaFuncSetAttribute(mma_gemm<false, false, false>,
                         cudaFuncAttributeMaxDynamicSharedMemorySize, SMEM_SZ);
    cudaFuncSetAttribute(mma_gemm<false, true, false>,
                         cudaFuncAttributeMaxDynamicSharedMemorySize, SMEM_SZ);
    cudaFuncSetAttribute(mma_gemm<true, false, false>,
                         cudaFuncAttributeMaxDynamicSharedMemorySize, SMEM_SZ);
    cudaFuncSetAttribute(mma_gemm<false, false, true>,
                         cudaFuncAttributeMaxDynamicSharedMemorySize, SMEM_SZ);

    // ---- static side streams + events (created once, on the uncaptured call) ----
    static cudaStream_t sA = nullptr, sBst = nullptr;
    static cudaEvent_t ev[8];
    if (!sA) {
        cudaStreamCreateWithFlags(&sA, cudaStreamNonBlocking);
        cudaStreamCreateWithFlags(&sBst, cudaStreamNonBlocking);
        for (int i = 0; i < 8; i++)
            cudaEventCreateWithFlags(&ev[i], cudaEventDisableTiming);
    }

    dim3 gBig(NN / 128, HH / 128);   // (256, 2)
    dim3 gXr(NN / 128, FD / 128);    // (256, 1)
    dim3 gAdj(NN / 128, 1);          // (256, 1)
    dim3 gPh(BB / 128, HH / 128);    // (2, 2)
    const int BA = NN * HH / 1024;   // bn_apply grid (8192)

    // ================= phase 1: convs (main) || CSR precompute (sA) ==========
    cudaEventRecord(ev[0], 0);
    cudaStreamWaitEvent(sA, ev[0], 0);
    cudaMemsetAsync(pDeg, 0, NN * sizeof(int), sA);
    k_count_deg<<<EE / 256, 256, 0, sA>>>(dst);
    k_scan_rows<<<BB, 128, 0, sA>>>();
    k_fill_csr<<<EE / 256, 256, 0, sA>>>(src, dst);
    cudaEventRecord(ev[1], sA);               // CSR ready

    a_conv<<<NN * FD / 1024, 256>>>(x, p0h, p0l, NN * FD / 4);
    WList wlist;
    wlist.w[0] = gcn_w0; wlist.kd[0] = FD; wlist.nd[0] = HH;
    wlist.w[1] = sc_w0;  wlist.kd[1] = FD; wlist.nd[1] = HH;
    wlist.w[2] = gcn_w1; wlist.kd[2] = HH; wlist.nd[2] = HH;
    wlist.w[3] = gcn_w2; wlist.kd[3] = HH; wlist.nd[3] = HH;
    wlist.w[4] = edge_w; wlist.kd[4] = HH; wlist.nd[4] = HH;
    wlist.w[5] = fd_w0;  wlist.kd[5] = HH; wlist.nd[5] = HH;
    wlist.w[6] = fd_w1;  wlist.kd[6] = HH; wlist.nd[6] = HH;
    wlist.w[7] = fd_w2;  wlist.kd[7] = HH; wlist.nd[7] = FD;
    wlist.w[8] = ph_w0;  wlist.kd[8] = HH; wlist.nd[8] = HH;
    wlist.w[9] = ph_w1;  wlist.kd[9] = HH; wlist.nd[9] = HH;
    w_conv_all<<<dim3(256, 10), 256>>>(wlist, wh, wl);
    cudaEventRecord(ev[2], 0);                // convs ready

    // sc0 GEMM on sBst, concurrent with gcn0 GEMM+agg on main
    cudaStreamWaitEvent(sBst, ev[2], 0);
    mma_gemm<false, false, false><<<gBig, 256, SMEM_SZ, sBst>>>(
        p0h, p0l, wh + 1 * 65536, wl + 1 * 65536,
        sc_b0, pSC, nullptr, nullptr, FD, HH, 0);
    cudaEventRecord(ev[3], sBst);             // shortcut ready

    // ---- block 0: fused gcn0 GEMM + aggregation + stats ----
    cudaMemsetAsync(pStats, 0, 2 * HH * sizeof(float), 0);
    cudaStreamWaitEvent(0, ev[1], 0);         // CSR needed by AGG epilogue
    mma_gemm<false, false, true><<<gBig, 256, SMEM_SZ>>>(
        p0h, p0l, wh + 0 * 65536, wl + 0 * 65536,
        nullptr, pB, nullptr, nullptr, FD, HH, 0);
    cudaStreamWaitEvent(0, ev[3], 0);         // shortcut residual
    bn_apply<<<BA, 256>>>(pB, pSC, bn_g0, bn_b0, pZ, p0h, p0l, 1);

    // ---- block 1 ----
    cudaMemsetAsync(pStats, 0, 2 * HH * sizeof(float), 0);
    mma_gemm<false, false, true><<<gBig, 256, SMEM_SZ>>>(
        p0h, p0l, wh + 2 * 65536, wl + 2 * 65536,
        nullptr, pB, nullptr, nullptr, HH, HH, 0);
    bn_apply<<<BA, 256>>>(pB, pZ, bn_g1, bn_b1, pZ, p0h, p0l, 1);

    // ---- block 2 ----
    cudaMemsetAsync(pStats, 0, 2 * HH * sizeof(float), 0);
    mma_gemm<false, false, true><<<gBig, 256, SMEM_SZ>>>(
        p0h, p0l, wh + 3 * 65536, wl + 3 * 65536,
        nullptr, pB, nullptr, nullptr, HH, HH, 0);
    bn_apply<<<BA, 256>>>(pB, pZ, bn_g2, bn_b2, pZ, nullptr, nullptr, 1);

    // ---- fused l2 normalize (output 0) + max pool (output 3) ----
    l2norm_pool<<<BB, 256>>>(pZ, out_z, p0h, p0l, out_zg, s0h, s0l);
    cudaEventRecord(ev[4], 0);                // z (fp32 + bf16) + z_g ready

    // ================= phase 2: three independent decoder chains =============
    // sA: edge decoder -> out_adj
    cudaStreamWaitEvent(sA, ev[4], 0);
    mma_gemm<false, false, false><<<gBig, 256, SMEM_SZ, sA>>>(
        p0h, p0l, wh + 4 * 65536, wl + 4 * 65536,
        nullptr, nullptr, p1h, p1l, HH, HH, 0);
    mma_gemm<true, false, false><<<gAdj, 256, SMEM_SZ, sA>>>(
        p1h, p1l, p0h, p0l,
        nullptr, out_adj, nullptr, nullptr, HH, MAXN, 0);
    cudaEventRecord(ev[5], sA);

    // sBst: pooling head -> out_mlp
    cudaStreamWaitEvent(sBst, ev[4], 0);
    mma_gemm<false, false, false><<<gPh, 256, SMEM_SZ, sBst>>>(
        s0h, s0l, wh + 8 * 65536, wl + 8 * 65536,
        ph_b0, nullptr, s1h, s1l, HH, HH, 1);
    mma_gemm<false, false, false><<<gPh, 256, SMEM_SZ, sBst>>>(
        s1h, s1l, wh + 9 * 65536, wl + 9 * 65536,
        ph_b1, out_mlp, nullptr, nullptr, HH, HH, 0);
    cudaEventRecord(ev[6], sBst);

    // main: feature decoder with BN folded into weights
    cudaMemsetAsync(pStats, 0, 2 * HH * sizeof(float), 0);
    mma_gemm<false, true, false><<<gBig, 256, SMEM_SZ>>>(
        p0h, p0l, wh + 5 * 65536, wl + 5 * 65536,
        fd_b0, nullptr, p2h, p2l, HH, HH, 1);
    fold_bn_w<<<HH, 256>>>(fd_w1, fd_b1, fd_g0, fd_be0, wfh, wfl, pBfold, HH);
    cudaMemsetAsync(pStats, 0, 2 * HH * sizeof(float), 0);
    mma_gemm<false, true, false><<<gBig, 256, SMEM_SZ>>>(
        p2h, p2l, wfh, wfl,
        pBfold, nullptr, p3h, p3l, HH, HH, 1);
    fold_bn_w<<<FD, 256>>>(fd_w2, fd_b2, fd_g1, fd_be1, wfh, wfl, pBfold, FD);
    mma_gemm<false, false, false><<<gXr, 256, SMEM_SZ>>>(
        p3h, p3l, wfh, wfl,
        pBfold, out_xr, nullptr, nullptr, HH, FD, 0);

    // join side streams back into the capture-origin stream
    cudaStreamWaitEvent(0, ev[5], 0);
    cudaStreamWaitEvent(0, ev[6], 0);
}

// round 13
// speedup vs baseline: 1.3016x; 1.0596x over previous
#include <cuda_runtime.h>
#include <cuda_bf16.h>
#include <math.h>
#include <stdint.h>

// Problem constants
#define NN   32768      // nodes
#define HH   256        // hidden
#define FD   128        // input feature dim
#define BB   256        // graphs
#define MAXN 128        // nodes per graph
#define EE   524288     // edges
#define EPG  2048       // edges per graph (EE/BB)

// ======================= PTX helpers (baseline compute_100 only) =======================
__device__ __forceinline__ uint32_t smem_to_u32(const void* smem_ptr) {
    uint32_t addr;
    asm("{ .reg .u64 tmp; cvta.to.shared.u64 tmp, %1; cvt.u32.u64 %0, tmp; }"
        : "=r"(addr) : "l"(smem_ptr));
    return addr;
}
__device__ __forceinline__ void ldsm4(uint32_t* r, uint32_t addr) {
    asm volatile("ldmatrix.sync.aligned.m8n8.x4.shared.b16 {%0,%1,%2,%3}, [%4];"
        : "=r"(r[0]), "=r"(r[1]), "=r"(r[2]), "=r"(r[3]) : "r"(addr));
}
__device__ __forceinline__ void mma16816(float* d, const uint32_t* a, uint32_t b0, uint32_t b1) {
    asm volatile(
        "mma.sync.aligned.m16n8k16.row.col.f32.bf16.bf16.f32 "
        "{%0,%1,%2,%3}, {%4,%5,%6,%7}, {%8,%9}, {%0,%1,%2,%3};"
        : "+f"(d[0]), "+f"(d[1]), "+f"(d[2]), "+f"(d[3])
        : "r"(a[0]), "r"(a[1]), "r"(a[2]), "r"(a[3]), "r"(b0), "r"(b1));
}
__device__ __forceinline__ void cp16(uint32_t s, const void* g) {
    asm volatile("cp.async.cg.shared.global [%0], [%1], 16;" :: "r"(s), "l"(g) : "memory");
}
__device__ __forceinline__ void cp_commit() {
    asm volatile("cp.async.commit_group;" ::: "memory");
}
template<int NG> __device__ __forceinline__ void cp_wait() {
    asm volatile("cp.async.wait_group %0;" :: "n"(NG) : "memory");
}

// ---------------- scratch (device globals) ----------------
__device__ __align__(256) float g_bufB[(size_t)NN * HH];
__device__ __align__(256) float g_z[(size_t)NN * HH];
__device__ __align__(256) float g_sc[(size_t)NN * HH];
__device__ float g_dinv[NN];
__device__ int   g_deg[NN];
__device__ int   g_rowstart[NN];
__device__ int   g_cursor[NN];
__device__ int   g_csr_src[EE];
__device__ float g_csr_norm[EE];
__device__ float g_stats[6 * 512];   // 6 slots x (256 sums | 256 sumsqs)
__device__ float g_bfold[HH];

// bf16 hi/lo operand buffers
__device__ __align__(256) __nv_bfloat16 g_p0hi[(size_t)NN * HH];
__device__ __align__(256) __nv_bfloat16 g_p0lo[(size_t)NN * HH];
__device__ __align__(256) __nv_bfloat16 g_p1hi[(size_t)NN * HH];
__device__ __align__(256) __nv_bfloat16 g_p1lo[(size_t)NN * HH];
__device__ __align__(256) __nv_bfloat16 g_p2hi[(size_t)NN * HH];
__device__ __align__(256) __nv_bfloat16 g_p2lo[(size_t)NN * HH];
__device__ __align__(256) __nv_bfloat16 g_p3hi[(size_t)NN * HH];
__device__ __align__(256) __nv_bfloat16 g_p3lo[(size_t)NN * HH];
__device__ __align__(256) __nv_bfloat16 g_s0hi[BB * HH];
__device__ __align__(256) __nv_bfloat16 g_s0lo[BB * HH];
__device__ __align__(256) __nv_bfloat16 g_s1hi[BB * HH];
__device__ __align__(256) __nv_bfloat16 g_s1lo[BB * HH];
__device__ __align__(256) __nv_bfloat16 g_whi[10 * 65536];  // 10 transposed weights
__device__ __align__(256) __nv_bfloat16 g_wlo[10 * 65536];
__device__ __align__(256) __nv_bfloat16 g_wfhi[65536];      // folded weight scratch
__device__ __align__(256) __nv_bfloat16 g_wflo[65536];

// ---------------- precompute: degrees, dinv, CSR ----------------
__global__ void k_count_deg(const int* __restrict__ dst) {
    int e = blockIdx.x * 256 + threadIdx.x;
    if (e >= EE) return;
    int g = e >> 11;
    atomicAdd(&g_deg[g * MAXN + dst[e]], 1);
}
__global__ void k_scan_rows() {
    int g = blockIdx.x;
    int t = threadIdx.x;
    int n = g * MAXN + t;
    __shared__ int s[MAXN];
    int d = g_deg[n];
    g_dinv[n] = rsqrtf((float)(d + 1));   // self loop adds 1
    s[t] = d;
    __syncthreads();
    for (int off = 1; off < MAXN; off <<= 1) {
        int v = (t >= off) ? s[t - off] : 0;
        __syncthreads();
        s[t] += v;
        __syncthreads();
    }
    int start = g * EPG + s[t] - d;
    g_rowstart[n] = start;
    g_cursor[n] = start;
}
__global__ void k_fill_csr(const int* __restrict__ src, const int* __restrict__ dst) {
    int e = blockIdx.x * 256 + threadIdx.x;
    if (e >= EE) return;
    int g = e >> 11;
    int s = src[e], d = dst[e];
    int slot = atomicAdd(&g_cursor[g * MAXN + d], 1);
    g_csr_src[slot] = s;
    g_csr_norm[slot] = g_dinv[g * MAXN + s] * g_dinv[g * MAXN + d];
}

// ---------------- fp32 -> bf16 hi/lo converts ----------------
__device__ __forceinline__ void split_bf16(float v, __nv_bfloat16& h, __nv_bfloat16& l) {
    h = __float2bfloat16(v);
    l = __float2bfloat16(v - __bfloat162float(h));
}
__device__ __forceinline__ void emit4(__nv_bfloat16* hi, __nv_bfloat16* lo, size_t o,
                                      float a, float b, float c, float d) {
    __nv_bfloat16 h0, l0, h1, l1, h2, l2, h3, l3;
    split_bf16(a, h0, l0); split_bf16(b, h1, l1);
    split_bf16(c, h2, l2); split_bf16(d, h3, l3);
    __nv_bfloat162 hv0 = {h0, h1}, hv1 = {h2, h3};
    __nv_bfloat162 lv0 = {l0, l1}, lv1 = {l2, l3};
    *(__nv_bfloat162*)(hi + o) = hv0;
    *(__nv_bfloat162*)(hi + o + 2) = hv1;
    *(__nv_bfloat162*)(lo + o) = lv0;
    *(__nv_bfloat162*)(lo + o + 2) = lv1;
}
__global__ void a_conv(const float* __restrict__ A, __nv_bfloat16* __restrict__ hi,
                       __nv_bfloat16* __restrict__ lo, int n4) {
    int i = blockIdx.x * 256 + threadIdx.x;
    if (i >= n4) return;
    float4 v = ((const float4*)A)[i];
    emit4(hi, lo, (size_t)i * 4, v.x, v.y, v.z, v.w);
}
struct WList { const float* w[10]; int kd[10]; int nd[10]; };
__global__ void w_conv_all(WList wl, __nv_bfloat16* __restrict__ hi,
                           __nv_bfloat16* __restrict__ lo) {
    int widx = blockIdx.y;
    int i = blockIdx.x * 256 + threadIdx.x;
    int Kd = wl.kd[widx], Nd = wl.nd[widx];
    if (i >= Kd * Nd) return;
    int k = i / Nd, n = i - k * Nd;
    __nv_bfloat16 h, l;
    split_bf16(wl.w[widx][i], h, l);
    hi[(size_t)widx * 65536 + (size_t)n * Kd + k] = h;
    lo[(size_t)widx * 65536 + (size_t)n * Kd + k] = l;
}

// ---- fold BN affine into next GEMM weights ----
__global__ void fold_bn_w(const float* __restrict__ W, const float* __restrict__ bias_in,
                          const float* __restrict__ gam, const float* __restrict__ bet,
                          const float* __restrict__ gstats,
                          __nv_bfloat16* __restrict__ whi, __nv_bfloat16* __restrict__ wlo,
                          float* __restrict__ bias_out, int Nd)
{
    __shared__ float red[256];
    int k = blockIdx.x;
    int j = threadIdx.x;
    const float invN = 1.0f / (float)NN;
    float m = gstats[j] * invN;
    float var = fmaxf(gstats[256 + j] * invN - m * m, 0.f);
    float a = gam[j] * rsqrtf(var + 1e-5f);
    float bp = bet[j] - m * a;
    float w = W[j * Nd + k];
    __nv_bfloat16 h, l;
    split_bf16(a * w, h, l);
    whi[(size_t)k * 256 + j] = h;
    wlo[(size_t)k * 256 + j] = l;
    red[j] = bp * w;
    __syncthreads();
    for (int o = 128; o > 0; o >>= 1) {
        if (j < o) red[j] += red[j + o];
        __syncthreads();
    }
    if (j == 0) bias_out[k] = bias_in[k] + red[0];
}

// ======================= mma.sync split-x3 GEMM =======================
// AGG: epilogue spills the 128x128 tile to smem and performs per-graph CSR
// aggregation + BN stats locally (blockIdx.x == graph id, blockIdx.y == col half).
#define ROWB   80
#define MATB   10240            // 128 rows * 80B
#define STAGEB 40960            // 4 matrices (Ahi,Alo,Bhi,Blo)
#define TSTRIDE 132             // padded tile row stride (floats)
template<bool ADJ, bool STATS, bool AGG>
__global__ void __launch_bounds__(256, 2)
mma_gemm(const __nv_bfloat16* __restrict__ Ahi, const __nv_bfloat16* __restrict__ Alo,
         const __nv_bfloat16* __restrict__ Bhi, const __nv_bfloat16* __restrict__ Blo,
         const float* __restrict__ bias, float* __restrict__ Cf,
         __nv_bfloat16* __restrict__ Chi, __nv_bfloat16* __restrict__ Clo,
         float* __restrict__ gstats,
         int K, int Ncols, int relu)
{
    extern __shared__ char smem[];
    const uint32_t sb = smem_to_u32(smem);
    const int tid = threadIdx.x;
    const int lane = tid & 31;
    const int wid = tid >> 5;
    const int warp_m = wid & 3;
    const int warp_n = wid >> 2;
    const int mrow0 = blockIdx.x * 128;
    const int bn0 = blockIdx.y * 128;
    const int brow0 = ADJ ? mrow0 : bn0;

    const __nv_bfloat16* baseA_hi = Ahi + (size_t)mrow0 * K;
    const __nv_bfloat16* baseA_lo = Alo + (size_t)mrow0 * K;
    const __nv_bfloat16* baseB_hi = Bhi + (size_t)brow0 * K;
    const __nv_bfloat16* baseB_lo = Blo + (size_t)brow0 * K;

    float acc[2][8][4];
#pragma unroll
    for (int mt = 0; mt < 2; mt++)
#pragma unroll
        for (int nt = 0; nt < 8; nt++)
#pragma unroll
            for (int v = 0; v < 4; v++) acc[mt][nt][v] = 0.f;

    auto load_chunk = [&](int c, int stage) {
        const int kc = c << 5;
        const uint32_t sbase = sb + stage * STAGEB;
#pragma unroll
        for (int t = 0; t < 8; t++) {
            int i = t * 256 + tid;
            int mat = i >> 9;
            int r = (i >> 2) & 127;
            int q = i & 3;
            const __nv_bfloat16* g;
            if      (mat == 0) g = baseA_hi + (size_t)r * K + kc + q * 8;
            else if (mat == 1) g = baseA_lo + (size_t)r * K + kc + q * 8;
            else if (mat == 2) g = baseB_hi + (size_t)r * K + kc + q * 8;
            else               g = baseB_lo + (size_t)r * K + kc + q * 8;
            cp16(sbase + mat * MATB + r * ROWB + q * 16, g);
        }
    };

    auto compute_chunk = [&](int stage) {
        const uint32_t sA = sb + stage * STAGEB;
        const uint32_t sB = sA + 2 * MATB;
#pragma unroll
        for (int ks = 0; ks < 2; ks++) {
            const uint32_t koff = ks * 32 + (lane >> 4) * 16;
            uint32_t ahi[2][4], alo[2][4];
#pragma unroll
            for (int mt = 0; mt < 2; mt++) {
                uint32_t ad = sA + (uint32_t)((warp_m * 32 + mt * 16 + (lane & 15)) * ROWB) + koff;
                ldsm4(ahi[mt], ad);
                ldsm4(alo[mt], ad + MATB);
            }
#pragma unroll
            for (int half = 0; half < 2; half++) {
                uint32_t bhiR[2][4], bloR[2][4];
#pragma unroll
                for (int g2 = 0; g2 < 2; g2++) {
                    uint32_t ad = sB + (uint32_t)((warp_n * 64 + (half * 2 + g2) * 16
                                   + (lane & 15)) * ROWB) + koff;
                    ldsm4(bhiR[g2], ad);
                    ldsm4(bloR[g2], ad + MATB);
                }
#pragma unroll
                for (int mt = 0; mt < 2; mt++)
#pragma unroll
                    for (int nt = 0; nt < 4; nt++) {
                        int g2 = nt >> 1, s = nt & 1;
                        float* ac = acc[mt][half * 4 + nt];
                        mma16816(ac, ahi[mt], bhiR[g2][s], bhiR[g2][s + 2]);
                        mma16816(ac, ahi[mt], bloR[g2][s], bloR[g2][s + 2]);
                        mma16816(ac, alo[mt], bhiR[g2][s], bhiR[g2][s + 2]);
                    }
            }
        }
    };

    const int nch = K >> 5;
    load_chunk(0, 0);
    cp_commit();
    for (int c = 0; c < nch; c++) {
        if (c + 1 < nch) {
            load_chunk(c + 1, (c + 1) & 1);
            cp_commit();
            cp_wait<1>();
        } else {
            cp_wait<0>();
        }
        __syncthreads();
        compute_chunk(c & 1);
        __syncthreads();
    }

    // ---- epilogue ----
    float* tile = (float*)smem;                    // AGG: 128 x TSTRIDE tile
    float* astat = tile + 128 * TSTRIDE;           // AGG: 256 floats (sum|sq)
    float* sst = (float*)smem;                     // STATS: 256 floats
    if (STATS || AGG) {
        if (tid < 256) (AGG ? astat : sst)[tid] = 0.f;
        if (STATS) __syncthreads();
    }
    float colsum[16], colsq[16];
    if (STATS) {
#pragma unroll
        for (int k = 0; k < 16; k++) { colsum[k] = 0.f; colsq[k] = 0.f; }
    }
    const int r0 = lane >> 2;
    const int cq = (lane & 3) * 2;
#pragma unroll
    for (int mt = 0; mt < 2; mt++) {
#pragma unroll
        for (int nt = 0; nt < 8; nt++) {
            int col = bn0 + warp_n * 64 + nt * 8 + cq;
            float bv0 = 0.f, bv1 = 0.f;
            if (bias) { bv0 = bias[col]; bv1 = bias[col + 1]; }
#pragma unroll
            for (int h = 0; h < 2; h++) {
                int row = mrow0 + warp_m * 32 + mt * 16 + r0 + h * 8;
                float v0 = acc[mt][nt][h * 2 + 0] + bv0;
                float v1 = acc[mt][nt][h * 2 + 1] + bv1;
                if (relu) { v0 = fmaxf(v0, 0.f); v1 = fmaxf(v1, 0.f); }
                if (STATS) {
                    colsum[nt * 2] += v0;     colsq[nt * 2] = fmaf(v0, v0, colsq[nt * 2]);
                    colsum[nt * 2 + 1] += v1; colsq[nt * 2 + 1] = fmaf(v1, v1, colsq[nt * 2 + 1]);
                }
                if (AGG) {
                    int rl = row - mrow0;
                    int cl = col - bn0;
                    *(float2*)&tile[rl * TSTRIDE + cl] = make_float2(v0, v1);
                } else if (ADJ) {
                    v0 = 1.f / (1.f + __expf(-v0));
                    v1 = 1.f / (1.f + __expf(-v1));
                    int rl = row - mrow0;
                    int cl = col;
                    if (rl == cl) v0 = 0.f;
                    if (rl == cl + 1) v1 = 0.f;
                    *(float2*)(Cf + (size_t)blockIdx.x * (MAXN * MAXN)
                               + (size_t)rl * MAXN + cl) = make_float2(v0, v1);
                } else {
                    size_t o = (size_t)row * Ncols + col;
                    if (Cf) *(float2*)(Cf + o) = make_float2(v0, v1);
                    if (Chi) {
                        __nv_bfloat16 h0, l0, h1, l1;
                        split_bf16(v0, h0, l0);
                        split_bf16(v1, h1, l1);
                        __nv_bfloat162 ph = {h0, h1}, pl = {l0, l1};
                        *(__nv_bfloat162*)(Chi + o) = ph;
                        *(__nv_bfloat162*)(Clo + o) = pl;
                    }
                }
            }
        }
    }
    if (AGG) {
        __syncthreads();
        // per-graph aggregation from the smem tile (rows = nodes of graph blockIdx.x)
        float ps0 = 0.f, ps1 = 0.f, ps2 = 0.f, ps3 = 0.f;
        float pq0 = 0.f, pq1 = 0.f, pq2 = 0.f, pq3 = 0.f;
        for (int n = wid; n < MAXN; n += 8) {
            int gn = mrow0 + n;
            int rs = g_rowstart[gn];
            int cnt = g_deg[gn];
            float di = g_dinv[gn];
            float sl = di * di;
            float4 self = *(const float4*)&tile[n * TSTRIDE + lane * 4];
            float a0 = self.x * sl, a1 = self.y * sl, a2 = self.z * sl, a3 = self.w * sl;
            for (int e = 0; e < cnt; e++) {
                int s = __ldg(&g_csr_src[rs + e]);
                float nm = __ldg(&g_csr_norm[rs + e]);
                float4 p = *(const float4*)&tile[s * TSTRIDE + lane * 4];
                a0 = fmaf(p.x, nm, a0);
                a1 = fmaf(p.y, nm, a1);
                a2 = fmaf(p.z, nm, a2);
                a3 = fmaf(p.w, nm, a3);
            }
            *(float4*)(Cf + (size_t)gn * HH + bn0 + lane * 4) = make_float4(a0, a1, a2, a3);
            ps0 += a0; ps1 += a1; ps2 += a2; ps3 += a3;
            pq0 = fmaf(a0, a0, pq0); pq1 = fmaf(a1, a1, pq1);
            pq2 = fmaf(a2, a2, pq2); pq3 = fmaf(a3, a3, pq3);
        }
        int c = lane * 4;
        atomicAdd(&astat[c + 0], ps0); atomicAdd(&astat[c + 1], ps1);
        atomicAdd(&astat[c + 2], ps2); atomicAdd(&astat[c + 3], ps3);
        atomicAdd(&astat[128 + c + 0], pq0); atomicAdd(&astat[128 + c + 1], pq1);
        atomicAdd(&astat[128 + c + 2], pq2); atomicAdd(&astat[128 + c + 3], pq3);
        __syncthreads();
        if (tid < 128) {
            atomicAdd(&gstats[bn0 + tid], astat[tid]);
            atomicAdd(&gstats[256 + bn0 + tid], astat[128 + tid]);
        }
    }
    if (STATS) {
#pragma unroll
        for (int nt = 0; nt < 8; nt++) {
            int cl = warp_n * 64 + nt * 8 + cq;
            atomicAdd(&sst[cl],           colsum[nt * 2]);
            atomicAdd(&sst[cl + 1],       colsum[nt * 2 + 1]);
            atomicAdd(&sst[128 + cl],     colsq[nt * 2]);
            atomicAdd(&sst[128 + cl + 1], colsq[nt * 2 + 1]);
        }
        __syncthreads();
        if (tid < 128) {
            atomicAdd(&gstats[bn0 + tid], sst[tid]);
            atomicAdd(&gstats[256 + bn0 + tid], sst[128 + tid]);
        }
    }
}

// ---------------- BatchNorm apply (vectorized, + bf16 emit) ----------------
// mode 0: out = bn(x); mode 1: out = relu(relu(bn(x)) + res). float4 per thread.
__global__ void bn_apply(const float* __restrict__ xin, const float* __restrict__ res,
                         const float* __restrict__ gam, const float* __restrict__ bet,
                         const float* __restrict__ gstats,
                         float* __restrict__ outp,
                         __nv_bfloat16* __restrict__ ohi, __nv_bfloat16* __restrict__ olo,
                         int mode)
{
    size_t i4 = ((size_t)blockIdx.x * 256 + threadIdx.x) * 4;
    int col = (int)(i4 & 255);
    const float invN = 1.0f / (float)NN;
    float a[4], bp[4];
#pragma unroll
    for (int k = 0; k < 4; k++) {
        float m = gstats[col + k] * invN;
        float var = fmaxf(gstats[256 + col + k] * invN - m * m, 0.f);
        float aa = gam[col + k] * rsqrtf(var + 1e-5f);
        a[k] = aa;
        bp[k] = bet[col + k] - m * aa;
    }
    float4 xv = *(const float4*)(xin + i4);
    float v[4] = { fmaf(xv.x, a[0], bp[0]), fmaf(xv.y, a[1], bp[1]),
                   fmaf(xv.z, a[2], bp[2]), fmaf(xv.w, a[3], bp[3]) };
    if (mode == 1) {
        float4 rv = *(const float4*)(res + i4);
        v[0] = fmaxf(fmaxf(v[0], 0.f) + rv.x, 0.f);
        v[1] = fmaxf(fmaxf(v[1], 0.f) + rv.y, 0.f);
        v[2] = fmaxf(fmaxf(v[2], 0.f) + rv.z, 0.f);
        v[3] = fmaxf(fmaxf(v[3], 0.f) + rv.w, 0.f);
    }
    if (outp) *(float4*)(outp + i4) = make_float4(v[0], v[1], v[2], v[3]);
    if (ohi) emit4(ohi, olo, i4, v[0], v[1], v[2], v[3]);
}

// ---------------- fused row L2 normalize + per-graph max pool ----------------
// Row-major float4 pass: warp w owns rows w, w+8, ...; per-thread column max
// (each thread touches fixed cols lane*4.. and 128+lane*4..) -> smem reduce.
__global__ void __launch_bounds__(256)
l2norm_pool(const float* __restrict__ zin, float* __restrict__ out_z,
            __nv_bfloat16* __restrict__ ohi, __nv_bfloat16* __restrict__ olo,
            float* __restrict__ out_zg,
            __nv_bfloat16* __restrict__ shi, __nv_bfloat16* __restrict__ slo)
{
    __shared__ float rinv[MAXN];
    __shared__ float wmax[8][HH];
    int g = blockIdx.x;
    int tid = threadIdx.x;
    int lane = tid & 31;
    int w = tid >> 5;
    const float* base = zin + (size_t)g * MAXN * HH;
    // pass 1: row norms
    for (int r = w; r < MAXN; r += 8) {
        const float4* p = (const float4*)(base + (size_t)r * HH);
        float4 v0 = p[lane], v1 = p[lane + 32];
        float s = v0.x * v0.x + v0.y * v0.y + v0.z * v0.z + v0.w * v0.w
                + v1.x * v1.x + v1.y * v1.y + v1.z * v1.z + v1.w * v1.w;
#pragma unroll
        for (int o = 16; o > 0; o >>= 1) s += __shfl_xor_sync(0xffffffffu, s, o);
        if (lane == 0) rinv[r] = 1.f / fmaxf(sqrtf(s), 1e-12f);
    }
    __syncthreads();
    // pass 2: normalize (row-major, vectorized) + per-thread column max
    float m0[4] = {-1e30f, -1e30f, -1e30f, -1e30f};
    float m1[4] = {-1e30f, -1e30f, -1e30f, -1e30f};
    for (int r = w; r < MAXN; r += 8) {
        float ri = rinv[r];
        const float4* p = (const float4*)(base + (size_t)r * HH);
        float4 v0 = p[lane], v1 = p[lane + 32];
        v0.x *= ri; v0.y *= ri; v0.z *= ri; v0.w *= ri;
        v1.x *= ri; v1.y *= ri; v1.z *= ri; v1.w *= ri;
        size_t ro = (size_t)(g * MAXN + r) * HH;
        ((float4*)(out_z + ro))[lane] = v0;
        ((float4*)(out_z + ro))[lane + 32] = v1;
        emit4(ohi, olo, ro + lane * 4, v0.x, v0.y, v0.z, v0.w);
        emit4(ohi, olo, ro + 128 + lane * 4, v1.x, v1.y, v1.z, v1.w);
        m0[0] = fmaxf(m0[0], v0.x); m0[1] = fmaxf(m0[1], v0.y);
        m0[2] = fmaxf(m0[2], v0.z); m0[3] = fmaxf(m0[3], v0.w);
        m1[0] = fmaxf(m1[0], v1.x); m1[1] = fmaxf(m1[1], v1.y);
        m1[2] = fmaxf(m1[2], v1.z); m1[3] = fmaxf(m1[3], v1.w);
    }
#pragma unroll
    for (int k = 0; k < 4; k++) {
        wmax[w][lane * 4 + k] = m0[k];
        wmax[w][128 + lane * 4 + k] = m1[k];
    }
    __syncthreads();
    // reduce 8 warps -> per-column max (256 threads, one column each)
    int c = tid;
    float mx = wmax[0][c];
#pragma unroll
    for (int ww = 1; ww < 8; ww++) mx = fmaxf(mx, wmax[ww][c]);
    int o2 = g * HH + c;
    out_zg[o2] = mx;
    __nv_bfloat16 h, l;
    split_bf16(mx, h, l);
    shi[o2] = h; slo[o2] = l;
}

// ---------------- launcher ----------------
extern "C" void kernel_launch(void* const* d_in, const int* in_sizes, int n_in,
                              void* d_out, int out_size)
{
    const float* x   = (const float*)d_in[0];
    const int*   src = (const int*)d_in[1];
    const int*   dst = (const int*)d_in[2];
    const float* gcn_w0 = (const float*)d_in[3];
    const float* bn_g0  = (const float*)d_in[5];
    const float* bn_b0  = (const float*)d_in[6];
    const float *sc_w0, *sc_b0, *gcn_w1, *bn_g1, *bn_b1, *gcn_w2, *bn_g2, *bn_b2;
    if (in_sizes[7] == FD * HH) {  // reference-signature order
        sc_w0  = (const float*)d_in[7];
        sc_b0  = (const float*)d_in[8];
        gcn_w1 = (const float*)d_in[9];
        bn_g1  = (const float*)d_in[11];
        bn_b1  = (const float*)d_in[12];
        gcn_w2 = (const float*)d_in[13];
        bn_g2  = (const float*)d_in[15];
        bn_b2  = (const float*)d_in[16];
    } else {                        // setup_inputs dict order
        gcn_w1 = (const float*)d_in[7];
        bn_g1  = (const float*)d_in[9];
        bn_b1  = (const float*)d_in[10];
        gcn_w2 = (const float*)d_in[11];
        bn_g2  = (const float*)d_in[13];
        bn_b2  = (const float*)d_in[14];
        sc_w0  = (const float*)d_in[15];
        sc_b0  = (const float*)d_in[16];
    }
    const float* edge_w = (const float*)d_in[17];
    const float* fd_w0  = (const float*)d_in[18];
    const float* fd_b0  = (const float*)d_in[19];
    const float* fd_g0  = (const float*)d_in[20];
    const float* fd_be0 = (const float*)d_in[21];
    const float* fd_w1  = (const float*)d_in[22];
    const float* fd_b1  = (const float*)d_in[23];
    const float* fd_g1  = (const float*)d_in[24];
    const float* fd_be1 = (const float*)d_in[25];
    const float* fd_w2  = (const float*)d_in[26];
    const float* fd_b2  = (const float*)d_in[27];
    const float* ph_w0  = (const float*)d_in[28];
    const float* ph_b0  = (const float*)d_in[29];
    const float* ph_w1  = (const float*)d_in[30];
    const float* ph_b1  = (const float*)d_in[31];

    float* out = (float*)d_out;
    float* out_z   = out;
    float* out_adj = out + (size_t)NN * HH;
    float* out_xr  = out_adj + (size_t)BB * MAXN * MAXN;
    float* out_zg  = out_xr + (size_t)NN * FD;
    float* out_mlp = out_zg + (size_t)BB * HH;

    float *pB, *pZ, *pSC, *pStats, *pBfold;
    int *pDeg;
    cudaGetSymbolAddress((void**)&pB, g_bufB);
    cudaGetSymbolAddress((void**)&pZ, g_z);
    cudaGetSymbolAddress((void**)&pSC, g_sc);
    cudaGetSymbolAddress((void**)&pStats, g_stats);
    cudaGetSymbolAddress((void**)&pDeg, g_deg);
    cudaGetSymbolAddress((void**)&pBfold, g_bfold);
    __nv_bfloat16 *p0h, *p0l, *p1h, *p1l, *p2h, *p2l, *p3h, *p3l;
    __nv_bfloat16 *s0h, *s0l, *s1h, *s1l, *wh, *wl, *wfh, *wfl;
    cudaGetSymbolAddress((void**)&p0h, g_p0hi);
    cudaGetSymbolAddress((void**)&p0l, g_p0lo);
    cudaGetSymbolAddress((void**)&p1h, g_p1hi);
    cudaGetSymbolAddress((void**)&p1l, g_p1lo);
    cudaGetSymbolAddress((void**)&p2h, g_p2hi);
    cudaGetSymbolAddress((void**)&p2l, g_p2lo);
    cudaGetSymbolAddress((void**)&p3h, g_p3hi);
    cudaGetSymbolAddress((void**)&p3l, g_p3lo);
    cudaGetSymbolAddress((void**)&s0h, g_s0hi);
    cudaGetSymbolAddress((void**)&s0l, g_s0lo);
    cudaGetSymbolAddress((void**)&s1h, g_s1hi);
    cudaGetSymbolAddress((void**)&s1l, g_s1lo);
    cudaGetSymbolAddress((void**)&wh, g_whi);
    cudaGetSymbolAddress((void**)&wl, g_wlo);
    cudaGetSymbolAddress((void**)&wfh, g_wfhi);
    cudaGetSymbolAddress((void**)&wfl, g_wflo);

    const int SMEM_SZ = 2 * STAGEB;      // 81920 (>= AGG tile 128*132*4 + 1KB)
    cudaFuncSetAttribute(mma_gemm<false, false, false>,
                         cudaFuncAttributeMaxDynamicSharedMemorySize, SMEM_SZ);
    cudaFuncSetAttribute(mma_gemm<false, true, false>,
                         cudaFuncAttributeMaxDynamicSharedMemorySize, SMEM_SZ);
    cudaFuncSetAttribute(mma_gemm<true, false, false>,
                         cudaFuncAttributeMaxDynamicSharedMemorySize, SMEM_SZ);
    cudaFuncSetAttribute(mma_gemm<false, false, true>,
                         cudaFuncAttributeMaxDynamicSharedMemorySize, SMEM_SZ);

    // ---- static side streams + events (created once, on the uncaptured call) ----
    static cudaStream_t sA = nullptr, sBst = nullptr;
    static cudaEvent_t ev[8];
    if (!sA) {
        cudaStreamCreateWithFlags(&sA, cudaStreamNonBlocking);
        cudaStreamCreateWithFlags(&sBst, cudaStreamNonBlocking);
        for (int i = 0; i < 8; i++)
            cudaEventCreateWithFlags(&ev[i], cudaEventDisableTiming);
    }

    dim3 gBig(NN / 128, HH / 128);   // (256, 2)
    dim3 gXr(NN / 128, FD / 128);    // (256, 1)
    dim3 gAdj(NN / 128, 1);          // (256, 1)
    dim3 gPh(BB / 128, HH / 128);    // (2, 2)
    const int BA = NN * HH / 1024;   // bn_apply grid (8192)

    // stats slots: 0,1,2 = gcn blocks; 3,4 = fd blocks
    float* st0 = pStats + 0 * 512;
    float* st1 = pStats + 1 * 512;
    float* st2 = pStats + 2 * 512;
    float* st3 = pStats + 3 * 512;
    float* st4 = pStats + 4 * 512;

    // ================= phase 1: convs (main) || CSR precompute (sA) ==========
    cudaEventRecord(ev[0], 0);
    cudaStreamWaitEvent(sA, ev[0], 0);
    cudaMemsetAsync(pDeg, 0, NN * sizeof(int), sA);
    k_count_deg<<<EE / 256, 256, 0, sA>>>(dst);
    k_scan_rows<<<BB, 128, 0, sA>>>();
    k_fill_csr<<<EE / 256, 256, 0, sA>>>(src, dst);
    cudaEventRecord(ev[1], sA);               // CSR ready

    cudaMemsetAsync(pStats, 0, 6 * 512 * sizeof(float), 0);  // all stat slots once
    a_conv<<<NN * FD / 1024, 256>>>(x, p0h, p0l, NN * FD / 4);
    WList wlist;
    wlist.w[0] = gcn_w0; wlist.kd[0] = FD; wlist.nd[0] = HH;
    wlist.w[1] = sc_w0;  wlist.kd[1] = FD; wlist.nd[1] = HH;
    wlist.w[2] = gcn_w1; wlist.kd[2] = HH; wlist.nd[2] = HH;
    wlist.w[3] = gcn_w2; wlist.kd[3] = HH; wlist.nd[3] = HH;
    wlist.w[4] = edge_w; wlist.kd[4] = HH; wlist.nd[4] = HH;
    wlist.w[5] = fd_w0;  wlist.kd[5] = HH; wlist.nd[5] = HH;
    wlist.w[6] = fd_w1;  wlist.kd[6] = HH; wlist.nd[6] = HH;
    wlist.w[7] = fd_w2;  wlist.kd[7] = HH; wlist.nd[7] = FD;
    wlist.w[8] = ph_w0;  wlist.kd[8] = HH; wlist.nd[8] = HH;
    wlist.w[9] = ph_w1;  wlist.kd[9] = HH; wlist.nd[9] = HH;
    w_conv_all<<<dim3(256, 10), 256>>>(wlist, wh, wl);
    cudaEventRecord(ev[2], 0);                // convs + stat-zero ready

    // sc0 GEMM on sBst, concurrent with gcn0 GEMM+agg on main
    cudaStreamWaitEvent(sBst, ev[2], 0);
    mma_gemm<false, false, false><<<gBig, 256, SMEM_SZ, sBst>>>(
        p0h, p0l, wh + 1 * 65536, wl + 1 * 65536,
        sc_b0, pSC, nullptr, nullptr, nullptr, FD, HH, 0);
    cudaEventRecord(ev[3], sBst);             // shortcut ready

    // ---- block 0: fused gcn0 GEMM + aggregation + stats ----
    cudaStreamWaitEvent(0, ev[1], 0);         // CSR needed by AGG epilogue
    mma_gemm<false, false, true><<<gBig, 256, SMEM_SZ>>>(
        p0h, p0l, wh + 0 * 65536, wl + 0 * 65536,
        nullptr, pB, nullptr, nullptr, st0, FD, HH, 0);
    cudaStreamWaitEvent(0, ev[3], 0);         // shortcut residual
    bn_apply<<<BA, 256>>>(pB, pSC, bn_g0, bn_b0, st0, pZ, p0h, p0l, 1);

    // ---- block 1 ----
    mma_gemm<false, false, true><<<gBig, 256, SMEM_SZ>>>(
        p0h, p0l, wh + 2 * 65536, wl + 2 * 65536,
        nullptr, pB, nullptr, nullptr, st1, HH, HH, 0);
    bn_apply<<<BA, 256>>>(pB, pZ, bn_g1, bn_b1, st1, pZ, p0h, p0l, 1);

    // ---- block 2 ----
    mma_gemm<false, false, true><<<gBig, 256, SMEM_SZ>>>(
        p0h, p0l, wh + 3 * 65536, wl + 3 * 65536,
        nullptr, pB, nullptr, nullptr, st2, HH, HH, 0);
    bn_apply<<<BA, 256>>>(pB, pZ, bn_g2, bn_b2, st2, pZ, nullptr, nullptr, 1);

    // ---- fused l2 normalize (output 0) + max pool (output 3) ----
    l2norm_pool<<<BB, 256>>>(pZ, out_z, p0h, p0l, out_zg, s0h, s0l);
    cudaEventRecord(ev[4], 0);                // z (fp32 + bf16) + z_g ready

    // ================= phase 2: three independent decoder chains =============
    // sA: edge decoder -> out_adj
    cudaStreamWaitEvent(sA, ev[4], 0);
    mma_gemm<false, false, false><<<gBig, 256, SMEM_SZ, sA>>>(
        p0h, p0l, wh + 4 * 65536, wl + 4 * 65536,
        nullptr, nullptr, p1h, p1l, nullptr, HH, HH, 0);
    mma_gemm<true, false, false><<<gAdj, 256, SMEM_SZ, sA>>>(
        p1h, p1l, p0h, p0l,
        nullptr, out_adj, nullptr, nullptr, nullptr, HH, MAXN, 0);
    cudaEventRecord(ev[5], sA);

    // sBst: pooling head -> out_mlp
    cudaStreamWaitEvent(sBst, ev[4], 0);
    mma_gemm<false, false, false><<<gPh, 256, SMEM_SZ, sBst>>>(
        s0h, s0l, wh + 8 * 65536, wl + 8 * 65536,
        ph_b0, nullptr, s1h, s1l, nullptr, HH, HH, 1);
    mma_gemm<false, false, false><<<gPh, 256, SMEM_SZ, sBst>>>(
        s1h, s1l, wh + 9 * 65536, wl + 9 * 65536,
        ph_b1, out_mlp, nullptr, nullptr, nullptr, HH, HH, 0);
    cudaEventRecord(ev[6], sBst);

    // main: feature decoder with BN folded into weights
    mma_gemm<false, true, false><<<gBig, 256, SMEM_SZ>>>(
        p0h, p0l, wh + 5 * 65536, wl + 5 * 65536,
        fd_b0, nullptr, p2h, p2l, st3, HH, HH, 1);
    fold_bn_w<<<HH, 256>>>(fd_w1, fd_b1, fd_g0, fd_be0, st3, wfh, wfl, pBfold, HH);
    mma_gemm<false, true, false><<<gBig, 256, SMEM_SZ>>>(
        p2h, p2l, wfh, wfl,
        pBfold, nullptr, p3h, p3l, st4, HH, HH, 1);
    fold_bn_w<<<FD, 256>>>(fd_w2, fd_b2, fd_g1, fd_be1, st4, wfh, wfl, pBfold, FD);
    mma_gemm<false, false, false><<<gXr, 256, SMEM_SZ>>>(
        p3h, p3l, wfh, wfl,
        pBfold, out_xr, nullptr, nullptr, nullptr, HH, FD, 0);

    // join side streams back into the capture-origin stream
    cudaStreamWaitEvent(0, ev[5], 0);
    cudaStreamWaitEvent(0, ev[6], 0);
}